// round 3
// baseline (speedup 1.0000x reference)
#include <cuda_runtime.h>
#include <cuda_bf16.h>
#include <cstdint>

#define DI __device__ __forceinline__
#define FULLMASK 0xFFFFFFFFu

// ===================== problem dims =====================
#define NBATCH 4
#define NPIX   4096          // 64*64
#define NCH    1792
#define NCENT  4096
#define M_TOT  (NBATCH*NPIX) // 16384
#define NNEI   200
#define SCORE_ELEMS (NBATCH*NNEI*NPIX)

// ===================== scratch (device globals) =====================
__device__ float g_pool0[4u*256*64*64];
__device__ float g_pool1[4u*512*32*32];
__device__ float g_pool2[4u*1024*16*16];
__device__ float g_conv0[4u*256*64*64];
__device__ float g_conv1[4u*512*32*32];
__device__ float g_conv2[4u*1024*16*16];
__device__ float g_res1 [4u*512*64*64];
__device__ float g_res2 [4u*1024*64*64];
__device__ __nv_bfloat16 g_phi[(size_t)M_TOT*NCH];
__device__ __nv_bfloat16 g_ct [(size_t)NCENT*NCH];
__device__ float g_feats[M_TOT];
__device__ float g_cents[NCENT];
__device__ float g_dist2[(size_t)M_TOT*NCENT];

// ===================== PTX helpers (sm_100 baseline ISA only) =====================
DI uint32_t smem_u32(const void* p) {
    uint32_t a;
    asm("{ .reg .u64 t; cvta.to.shared.u64 t, %1; cvt.u32.u64 %0, t; }" : "=r"(a) : "l"(p));
    return a;
}
DI void ldsm4(uint32_t* r, uint32_t a) {
    asm volatile("ldmatrix.sync.aligned.m8n8.x4.shared.b16 {%0,%1,%2,%3}, [%4];"
        : "=r"(r[0]), "=r"(r[1]), "=r"(r[2]), "=r"(r[3]) : "r"(a));
}
DI void mma16816(float* c, const uint32_t* a, uint32_t b0, uint32_t b1) {
    asm volatile("mma.sync.aligned.m16n8k16.row.col.f32.bf16.bf16.f32 "
        "{%0,%1,%2,%3}, {%4,%5,%6,%7}, {%8,%9}, {%0,%1,%2,%3};"
        : "+f"(c[0]), "+f"(c[1]), "+f"(c[2]), "+f"(c[3])
        : "r"(a[0]), "r"(a[1]), "r"(a[2]), "r"(a[3]), "r"(b0), "r"(b1));
}
DI void cpasync16(uint32_t dst, const void* src) {
    asm volatile("cp.async.cg.shared.global [%0], [%1], 16;" :: "r"(dst), "l"(src) : "memory");
}
DI void cp_commit() { asm volatile("cp.async.commit_group;" ::: "memory"); }
DI void cp_wait1()  { asm volatile("cp.async.wait_group 1;" ::: "memory"); }
DI void cp_wait0()  { asm volatile("cp.async.wait_group 0;" ::: "memory"); }

// ===================== 1) avg_pool 3x3 stride1 pad1, /9 =====================
__global__ void avgpool3_kernel(const float* __restrict__ x, float* __restrict__ y,
                                int H, int W, int total) {
    int idx = blockIdx.x * 256 + threadIdx.x;
    if (idx >= total) return;
    int w = idx % W;
    int h = (idx / W) % H;
    int bc = idx / (W * H);
    const float* p = x + (size_t)bc * H * W;
    float s = 0.f;
    #pragma unroll
    for (int dy = -1; dy <= 1; dy++) {
        int hh = h + dy;
        if (hh < 0 || hh >= H) continue;
        #pragma unroll
        for (int dx = -1; dx <= 1; dx++) {
            int ww = w + dx;
            if (ww < 0 || ww >= W) continue;
            s += p[hh * W + ww];
        }
    }
    y[idx] = s * (1.0f / 9.0f);
}

// ===================== 2) coord-conv 1x1 (fp32 tiled GEMM) =====================
__global__ __launch_bounds__(256) void coordconv_kernel(
    const float* __restrict__ x, const float* __restrict__ w, const float* __restrict__ bias,
    float* __restrict__ o, int C, int OC, int H, int W) {
    __shared__ float Xs[16 * 64];
    __shared__ float Ws[16 * 68];
    int b = blockIdx.z;
    int p0 = blockIdx.x * 64, oc0 = blockIdx.y * 64;
    int HW = H * W;
    int t = threadIdx.x;
    int tx = t & 15, ty = t >> 4;
    int Cp2 = C + 2;
    float acc[4][4] = {};
    for (int k0 = 0; k0 < C; k0 += 16) {
        int idx = t;
        #pragma unroll
        for (int i = 0; i < 4; i++, idx += 256) {
            int kk = idx >> 6, pp = idx & 63;
            Xs[kk * 64 + pp] = x[(size_t)(b * C + k0 + kk) * HW + p0 + pp];
        }
        idx = t;
        #pragma unroll
        for (int i = 0; i < 4; i++, idx += 256) {
            int ocp = idx >> 4, kk = idx & 15;
            Ws[kk * 68 + ocp] = w[(size_t)(oc0 + ocp) * Cp2 + k0 + kk];
        }
        __syncthreads();
        #pragma unroll
        for (int kk = 0; kk < 16; kk++) {
            float a4[4], b4[4];
            #pragma unroll
            for (int j = 0; j < 4; j++) a4[j] = Xs[kk * 64 + tx * 4 + j];
            #pragma unroll
            for (int i = 0; i < 4; i++) b4[i] = Ws[kk * 68 + ty * 4 + i];
            #pragma unroll
            for (int i = 0; i < 4; i++)
                #pragma unroll
                for (int j = 0; j < 4; j++)
                    acc[i][j] += b4[i] * a4[j];
        }
        __syncthreads();
    }
    float invW = 2.f / (float)(W - 1), invH = 2.f / (float)(H - 1);
    #pragma unroll
    for (int i = 0; i < 4; i++) {
        int oc = oc0 + ty * 4 + i;
        float cx = w[(size_t)oc * Cp2 + C];
        float cy = w[(size_t)oc * Cp2 + C + 1];
        float bb = bias[oc];
        #pragma unroll
        for (int j = 0; j < 4; j++) {
            int p = p0 + tx * 4 + j;
            float xg = -1.f + (float)(p % W) * invW;
            float yg = -1.f + (float)(p / W) * invH;
            o[(size_t)(b * OC + oc) * HW + p] = acc[i][j] + cx * xg + cy * yg + bb;
        }
    }
}

// ===================== 3) bilinear resize SxS -> 64x64 (half-pixel, clamp) =====================
__global__ void resize_kernel(const float* __restrict__ src, float* __restrict__ dst, int S) {
    int plane = blockIdx.x;
    const float* sp = src + (size_t)plane * S * S;
    float* dp = dst + (size_t)plane * 4096;
    float sc = (float)S / 64.f;
    for (int idx = threadIdx.x; idx < 4096; idx += 256) {
        int h = idx >> 6, ww = idx & 63;
        float fy = (h + 0.5f) * sc - 0.5f; fy = fminf(fmaxf(fy, 0.f), (float)(S - 1));
        float fx = (ww + 0.5f) * sc - 0.5f; fx = fminf(fmaxf(fx, 0.f), (float)(S - 1));
        int y0 = (int)fy, x0 = (int)fx;
        int y1 = min(y0 + 1, S - 1), x1 = min(x0 + 1, S - 1);
        float wy = fy - (float)y0, wx = fx - (float)x0;
        float v00 = sp[y0 * S + x0], v01 = sp[y0 * S + x1];
        float v10 = sp[y1 * S + x0], v11 = sp[y1 * S + x1];
        dp[idx] = (1.f - wy) * ((1.f - wx) * v00 + wx * v01) + wy * ((1.f - wx) * v10 + wx * v11);
    }
}

DI float fetch_chan(const float* __restrict__ c0, const float* __restrict__ r1,
                    const float* __restrict__ r2, int b, int ch, int p) {
    if (ch < 256)  return c0[(((size_t)(b * 256  + ch))       << 12) + p];
    if (ch < 768)  return r1[(((size_t)(b * 512  + ch - 256)) << 12) + p];
    return r2[(((size_t)(b * 1024 + ch - 768)) << 12) + p];
}

__global__ void zero_kernel(float* p, int n) {
    int i = blockIdx.x * 256 + threadIdx.x;
    if (i < n) p[i] = 0.f;
}

// ===================== 4) transpose to phi (bf16, K-major) + feats =====================
__global__ void phi_kernel(const float* __restrict__ c0, const float* __restrict__ r1,
                           const float* __restrict__ r2) {
    __shared__ float tile[32][33];
    int b = blockIdx.z, ch0 = blockIdx.x * 32, p0 = blockIdx.y * 32;
    int tx = threadIdx.x, ty = threadIdx.y;
    for (int i = ty; i < 32; i += 8)
        tile[i][tx] = fetch_chan(c0, r1, r2, b, ch0 + i, p0 + tx);
    __syncthreads();
    for (int i = ty; i < 32; i += 8) {
        int p = p0 + i;
        float v = tile[tx][i];
        g_phi[(size_t)(b * 4096 + p) * NCH + ch0 + tx] = __float2bfloat16(v);
        float s = v * v;
        s += __shfl_xor_sync(FULLMASK, s, 16);
        s += __shfl_xor_sync(FULLMASK, s, 8);
        s += __shfl_xor_sync(FULLMASK, s, 4);
        s += __shfl_xor_sync(FULLMASK, s, 2);
        s += __shfl_xor_sync(FULLMASK, s, 1);
        if (tx == 0) atomicAdd(&g_feats[b * 4096 + p], s);
    }
}

// ===================== 5) out2 = PHI[:, :896] =====================
__global__ void out2_kernel(const float* __restrict__ c0, const float* __restrict__ r1,
                            const float* __restrict__ r2, float* __restrict__ out2) {
    int ch = blockIdx.x, b = blockIdx.y;
    for (int p = threadIdx.x; p < 4096; p += 256)
        out2[(((size_t)(b * 896 + ch)) << 12) + p] = fetch_chan(c0, r1, r2, b, ch, p);
}

// ===================== 6) cents + C transpose (bf16) =====================
__global__ void cents_kernel(const float* __restrict__ C) {
    int j = blockIdx.x * 256 + threadIdx.x;
    float s = 0.f;
    #pragma unroll 8
    for (int k = 0; k < NCH; k++) {
        float v = C[(size_t)k * 4096 + j];
        s += v * v;
    }
    g_cents[j] = s;
}

__global__ void tposeC_kernel(const float* __restrict__ C) {
    __shared__ float tile[32][33];
    int j0 = blockIdx.x * 32, k0 = blockIdx.y * 32;
    int tx = threadIdx.x, ty = threadIdx.y;
    for (int i = ty; i < 32; i += 8)
        tile[i][tx] = C[(size_t)(k0 + i) * 4096 + j0 + tx];
    __syncthreads();
    for (int i = ty; i < 32; i += 8)
        g_ct[(size_t)(j0 + i) * NCH + k0 + tx] = __float2bfloat16(tile[tx][i]);
}

// ===================== 7) distance GEMM (mma.sync bf16, 128x128 tile, K-chunk 32) =====================
// smem row stride: 40 halves = 80B (conflict-free ldmatrix: 20*r mod 32 distinct per 8 rows)
#define AS_BYTES  (128*80)
#define BUF_BYTES (2*AS_BYTES)
#define NKCHUNK   (NCH/32)   // 56

DI void gemm_load_chunk(uint32_t sA, uint32_t sB, int m0, int n0, int k0, int t) {
    // A: 128 rows x 32 k = 512 x 16B ; 2 per thread
    #pragma unroll
    for (int i = 0; i < 2; i++) {
        int idx = t + i * 256;
        int row = idx >> 2, seg = idx & 3;
        cpasync16(sA + row * 80 + seg * 16,
                  &g_phi[(size_t)(m0 + row) * NCH + k0 + seg * 8]);
    }
    // B: 128 rows x 32 k
    #pragma unroll
    for (int i = 0; i < 2; i++) {
        int idx = t + i * 256;
        int row = idx >> 2, seg = idx & 3;
        cpasync16(sB + row * 80 + seg * 16,
                  &g_ct[(size_t)(n0 + row) * NCH + k0 + seg * 8]);
    }
    cp_commit();
}

__global__ __launch_bounds__(256) void gemm_kernel() {
    __shared__ __align__(16) char smem[2 * BUF_BYTES];
    const uint32_t sbase = smem_u32(smem);
    int t = threadIdx.x, lane = t & 31, wid = t >> 5;
    int wm = wid & 1, wn = wid >> 1;           // 2 x 4 warp grid; warp tile 64x32
    int m0 = blockIdx.x * 128, n0 = blockIdx.y * 128;

    float c[4][4][4];
    #pragma unroll
    for (int i = 0; i < 4; i++)
        #pragma unroll
        for (int j = 0; j < 4; j++)
            #pragma unroll
            for (int r = 0; r < 4; r++) c[i][j][r] = 0.f;

    // ldmatrix base addresses (per-thread, buffer 0)
    const uint32_t a_row = wm * 64 + (lane & 15);
    const uint32_t a_base = a_row * 80 + ((lane >> 4) * 16);
    const uint32_t b_row = wn * 32 + ((lane >> 4) * 8) + (lane & 7);
    const uint32_t b_base = b_row * 80 + (((lane >> 3) & 1) * 16);

    gemm_load_chunk(sbase, sbase + AS_BYTES, m0, n0, 0, t);

    #pragma unroll 1
    for (int ck = 0; ck < NKCHUNK; ck++) {
        int buf = ck & 1;
        if (ck + 1 < NKCHUNK) {
            int ob = buf ^ 1;
            gemm_load_chunk(sbase + ob * BUF_BYTES, sbase + ob * BUF_BYTES + AS_BYTES,
                            m0, n0, (ck + 1) * 32, t);
            cp_wait1();
        } else {
            cp_wait0();
        }
        __syncthreads();

        uint32_t sA = sbase + buf * BUF_BYTES;
        uint32_t sB = sA + AS_BYTES;
        #pragma unroll
        for (int ks = 0; ks < 2; ks++) {
            uint32_t a[4][4];
            #pragma unroll
            for (int mi = 0; mi < 4; mi++)
                ldsm4(a[mi], sA + a_base + mi * (16 * 80) + ks * 32);
            uint32_t bfr[2][4];
            #pragma unroll
            for (int np = 0; np < 2; np++)
                ldsm4(bfr[np], sB + b_base + np * (16 * 80) + ks * 32);
            #pragma unroll
            for (int mi = 0; mi < 4; mi++)
                #pragma unroll
                for (int np = 0; np < 2; np++) {
                    mma16816(c[mi][np * 2 + 0], a[mi], bfr[np][0], bfr[np][1]);
                    mma16816(c[mi][np * 2 + 1], a[mi], bfr[np][2], bfr[np][3]);
                }
        }
        __syncthreads();
    }

    // epilogue: dist2 = feats + cents - 2*acc
    #pragma unroll
    for (int mi = 0; mi < 4; mi++) {
        int r0 = m0 + wm * 64 + mi * 16 + (lane >> 2);
        float f0 = g_feats[r0], f1 = g_feats[r0 + 8];
        #pragma unroll
        for (int ni = 0; ni < 4; ni++) {
            int cc = n0 + wn * 32 + ni * 8 + (lane & 3) * 2;
            float ce0 = g_cents[cc], ce1 = g_cents[cc + 1];
            float* dp = &g_dist2[(size_t)r0 * 4096 + cc];
            float2 v0 = { f0 + ce0 - 2.f * c[mi][ni][0], f0 + ce1 - 2.f * c[mi][ni][1] };
            float2 v1 = { f1 + ce0 - 2.f * c[mi][ni][2], f1 + ce1 - 2.f * c[mi][ni][3] };
            *reinterpret_cast<float2*>(dp) = v0;
            *reinterpret_cast<float2*>(dp + (size_t)8 * 4096) = v1;
        }
    }
}

// ===================== 8) top-200 per row: radix select + bitonic sort =====================
__global__ __launch_bounds__(256) void topk_kernel(const float* __restrict__ dist2,
                                                   float* __restrict__ out) {
    __shared__ float keys[4096];
    __shared__ unsigned hist[256];
    __shared__ unsigned scan[256];
    __shared__ unsigned sh_want, sh_prefix;
    __shared__ unsigned cnt_lt;
    __shared__ float sel[256];

    int row = blockIdx.x;
    int t = threadIdx.x;
    int lane = t & 31;
    const float* src = dist2 + (size_t)row * 4096;
    for (int i = t; i < 4096; i += 256) keys[i] = src[i];
    if (t == 0) { sh_want = NNEI; sh_prefix = 0; cnt_lt = 0; }
    __syncthreads();

    for (int pass = 0; pass < 4; pass++) {
        int shift = 24 - pass * 8;
        unsigned pfx = sh_prefix;
        unsigned want = sh_want;
        hist[t] = 0;
        __syncthreads();
        for (int i = t; i < 4096; i += 256) {
            unsigned u = __float_as_uint(keys[i]);
            bool ok = (pass == 0) || ((u >> (shift + 8)) == pfx);
            unsigned d = ok ? ((u >> shift) & 255u) : 0x100u;
            unsigned m = __match_any_sync(FULLMASK, d);
            if (ok && ((m & ((1u << lane) - 1u)) == 0))
                atomicAdd(&hist[d], (unsigned)__popc(m));
        }
        __syncthreads();
        scan[t] = hist[t];
        __syncthreads();
        for (int off = 1; off < 256; off <<= 1) {
            unsigned x = (t >= off) ? scan[t - off] : 0u;
            __syncthreads();
            scan[t] += x;
            __syncthreads();
        }
        unsigned below = (t == 0) ? 0u : scan[t - 1];
        if (below < want && want <= scan[t]) {
            sh_want = want - below;
            sh_prefix = (pfx << 8) | (unsigned)t;
        }
        __syncthreads();
    }

    unsigned Tb = sh_prefix;
    float Tf = __uint_as_float(Tb);
    for (int i = t; i < 4096; i += 256) {
        float v = keys[i];
        if (v < Tf) {
            unsigned pos = atomicAdd(&cnt_lt, 1u);
            sel[pos] = v;
        }
    }
    __syncthreads();
    unsigned base = cnt_lt;   // == 200 - (#copies of T needed)
    if ((unsigned)t >= base) sel[t] = (t < NNEI) ? Tf : __int_as_float(0x7f800000);
    __syncthreads();

    // bitonic sort 256 ascending
    for (int k = 2; k <= 256; k <<= 1) {
        for (int j = k >> 1; j > 0; j >>= 1) {
            int ixj = t ^ j;
            if (ixj > t) {
                bool up = ((t & k) == 0);
                float a = sel[t], b = sel[ixj];
                if ((a > b) == up) { sel[t] = b; sel[ixj] = a; }
            }
            __syncthreads();
        }
    }

    if (t < NNEI) {
        int b = row >> 12, p = row & 4095;
        out[(((size_t)(b * NNEI + t)) << 12) + p] = sqrtf(sel[t]);
    }
}

// ===================== host launcher =====================
extern "C" void kernel_launch(void* const* d_in, const int* in_sizes, int n_in,
                              void* d_out, int out_size) {
    const float* p0 = (const float*)d_in[0];
    const float* p1 = (const float*)d_in[1];
    const float* p2 = (const float*)d_in[2];
    const float* w1 = (const float*)d_in[5];
    const float* b1 = (const float*)d_in[6];
    const float* w2 = (const float*)d_in[7];
    const float* b2 = (const float*)d_in[8];
    const float* w3 = (const float*)d_in[9];
    const float* b3 = (const float*)d_in[10];
    const float* Cm = (const float*)d_in[11];
    float* score = (float*)d_out;
    float* out2  = score + SCORE_ELEMS;

    void *pool0, *pool1, *pool2, *conv0, *conv1, *conv2, *res1, *res2, *feats, *dist2;
    cudaGetSymbolAddress(&pool0, g_pool0);
    cudaGetSymbolAddress(&pool1, g_pool1);
    cudaGetSymbolAddress(&pool2, g_pool2);
    cudaGetSymbolAddress(&conv0, g_conv0);
    cudaGetSymbolAddress(&conv1, g_conv1);
    cudaGetSymbolAddress(&conv2, g_conv2);
    cudaGetSymbolAddress(&res1,  g_res1);
    cudaGetSymbolAddress(&res2,  g_res2);
    cudaGetSymbolAddress(&feats, g_feats);
    cudaGetSymbolAddress(&dist2, g_dist2);

    // 1) avgpool
    avgpool3_kernel<<<(4*256*4096 + 255)/256, 256>>>(p0, (float*)pool0, 64, 64, 4*256*4096);
    avgpool3_kernel<<<(4*512*1024 + 255)/256, 256>>>(p1, (float*)pool1, 32, 32, 4*512*1024);
    avgpool3_kernel<<<(4*1024*256 + 255)/256, 256>>>(p2, (float*)pool2, 16, 16, 4*1024*256);

    // 2) coord-conv 1x1
    coordconv_kernel<<<dim3(64, 4, 4),  256>>>((const float*)pool0, w1, b1, (float*)conv0, 256, 256, 64, 64);
    coordconv_kernel<<<dim3(16, 8, 4),  256>>>((const float*)pool1, w2, b2, (float*)conv1, 512, 512, 32, 32);
    coordconv_kernel<<<dim3(4, 16, 4),  256>>>((const float*)pool2, w3, b3, (float*)conv2, 1024, 1024, 16, 16);

    // 3) resize levels 1/2 to 64x64 (p-major)
    resize_kernel<<<4*512,  256>>>((const float*)conv1, (float*)res1, 32);
    resize_kernel<<<4*1024, 256>>>((const float*)conv2, (float*)res2, 16);

    // 4) phi (bf16 transpose) + feats
    zero_kernel<<<(M_TOT + 255)/256, 256>>>((float*)feats, M_TOT);
    phi_kernel<<<dim3(NCH/32, 4096/32, 4), dim3(32, 8)>>>((const float*)conv0, (const float*)res1, (const float*)res2);

    // 5) out2 = PHI[:, :896]
    out2_kernel<<<dim3(896, 4), 256>>>((const float*)conv0, (const float*)res1, (const float*)res2, out2);

    // 6) cents + C transpose
    cents_kernel<<<NCENT/256, 256>>>(Cm);
    tposeC_kernel<<<dim3(4096/32, NCH/32), dim3(32, 8)>>>(Cm);

    // 7) distance GEMM (mma.sync path — tcgen05 unavailable on plain sm_100 target)
    gemm_kernel<<<dim3(M_TOT/128, NCENT/128), 256>>>();

    // 8) top-200
    topk_kernel<<<M_TOT, 256>>>((const float*)dist2, score);
}

// round 4
// speedup vs baseline: 1.1261x; 1.1261x over previous
#include <cuda_runtime.h>
#include <cuda_bf16.h>
#include <cstdint>

#define DI __device__ __forceinline__
#define FULLMASK 0xFFFFFFFFu

// ===================== problem dims =====================
#define NBATCH 4
#define NPIX   4096
#define NCH    1792
#define NCENT  4096
#define M_TOT  (NBATCH*NPIX)
#define NNEI   200
#define SCORE_ELEMS (NBATCH*NNEI*NPIX)

// ===================== scratch =====================
__device__ float g_pool0[4u*256*64*64];
__device__ float g_pool1[4u*512*32*32];
__device__ float g_pool2[4u*1024*16*16];
__device__ float g_conv0[4u*256*64*64];
__device__ float g_conv1[4u*512*32*32];
__device__ float g_conv2[4u*1024*16*16];
__device__ __nv_bfloat16 g_phi[(size_t)M_TOT*NCH];
__device__ __nv_bfloat16 g_ct [(size_t)NCENT*NCH];
__device__ float g_feats[M_TOT];
__device__ float g_cents[NCENT];
__device__ float g_dist2[(size_t)M_TOT*NCENT];

// ===================== PTX helpers (sm_100 baseline ISA) =====================
DI uint32_t smem_u32(const void* p) {
    uint32_t a;
    asm("{ .reg .u64 t; cvta.to.shared.u64 t, %1; cvt.u32.u64 %0, t; }" : "=r"(a) : "l"(p));
    return a;
}
DI void ldsm4(uint32_t* r, uint32_t a) {
    asm volatile("ldmatrix.sync.aligned.m8n8.x4.shared.b16 {%0,%1,%2,%3}, [%4];"
        : "=r"(r[0]), "=r"(r[1]), "=r"(r[2]), "=r"(r[3]) : "r"(a));
}
DI void mma16816(float* c, const uint32_t* a, uint32_t b0, uint32_t b1) {
    asm volatile("mma.sync.aligned.m16n8k16.row.col.f32.bf16.bf16.f32 "
        "{%0,%1,%2,%3}, {%4,%5,%6,%7}, {%8,%9}, {%0,%1,%2,%3};"
        : "+f"(c[0]), "+f"(c[1]), "+f"(c[2]), "+f"(c[3])
        : "r"(a[0]), "r"(a[1]), "r"(a[2]), "r"(a[3]), "r"(b0), "r"(b1));
}
DI void cpasync16(uint32_t dst, const void* src) {
    asm volatile("cp.async.cg.shared.global [%0], [%1], 16;" :: "r"(dst), "l"(src) : "memory");
}
DI void cp_commit() { asm volatile("cp.async.commit_group;" ::: "memory"); }
DI void cp_wait1()  { asm volatile("cp.async.wait_group 1;" ::: "memory"); }
DI void cp_wait0()  { asm volatile("cp.async.wait_group 0;" ::: "memory"); }

// ===================== launch 1: prep mega-kernel =====================
// blocks: [0,16384) pool0 | [16384,24576) pool1 | [24576,28672) pool2 |
//         [28672,35840) C-transpose | [35840,35856) cents | [35856,35920) zero feats
DI void pool_body(const float* __restrict__ x, float* __restrict__ y,
                  int H, int W, int idx) {
    int w = idx % W;
    int h = (idx / W) % H;
    int bc = idx / (W * H);
    const float* p = x + (size_t)bc * H * W;
    float s = 0.f;
    #pragma unroll
    for (int dy = -1; dy <= 1; dy++) {
        int hh = h + dy;
        if (hh < 0 || hh >= H) continue;
        #pragma unroll
        for (int dx = -1; dx <= 1; dx++) {
            int ww = w + dx;
            if (ww < 0 || ww >= W) continue;
            s += p[hh * W + ww];
        }
    }
    y[idx] = s * (1.0f / 9.0f);
}

__global__ __launch_bounds__(256) void prep_kernel(
    const float* __restrict__ p0, const float* __restrict__ p1,
    const float* __restrict__ p2, const float* __restrict__ C) {
    int bb = blockIdx.x, t = threadIdx.x;
    if (bb < 16384) {
        pool_body(p0, g_pool0, 64, 64, bb * 256 + t);
    } else if (bb < 24576) {
        pool_body(p1, g_pool1, 32, 32, (bb - 16384) * 256 + t);
    } else if (bb < 28672) {
        pool_body(p2, g_pool2, 16, 16, (bb - 24576) * 256 + t);
    } else if (bb < 35840) {
        __shared__ float tile[32][33];
        int id = bb - 28672;
        int j0 = (id & 127) * 32, k0 = (id >> 7) * 32;
        int tx = t & 31, ty = t >> 5;
        for (int i = ty; i < 32; i += 8)
            tile[i][tx] = C[(size_t)(k0 + i) * 4096 + j0 + tx];
        __syncthreads();
        for (int i = ty; i < 32; i += 8)
            g_ct[(size_t)(j0 + i) * NCH + k0 + tx] = __float2bfloat16(tile[tx][i]);
    } else if (bb < 35856) {
        int j = (bb - 35840) * 256 + t;
        float s = 0.f;
        #pragma unroll 8
        for (int k = 0; k < NCH; k++) {
            float v = C[(size_t)k * 4096 + j];
            s += v * v;
        }
        g_cents[j] = s;
    } else {
        g_feats[(bb - 35856) * 256 + t] = 0.f;
    }
}

// ===================== launch 2: coord-conv all levels =====================
DI void conv_body(const float* __restrict__ x, const float* __restrict__ w,
                  const float* __restrict__ bias, float* __restrict__ o,
                  int C, int OC, int H, int W, int b, int px, int ocb,
                  float* Xs, float* Ws, int t) {
    int p0 = px * 64, oc0 = ocb * 64;
    int HW = H * W;
    int tx = t & 15, ty = t >> 4;
    int Cp2 = C + 2;
    float acc[4][4] = {};
    for (int k0 = 0; k0 < C; k0 += 16) {
        int idx = t;
        #pragma unroll
        for (int i = 0; i < 4; i++, idx += 256) {
            int kk = idx >> 6, pp = idx & 63;
            Xs[kk * 64 + pp] = x[(size_t)(b * C + k0 + kk) * HW + p0 + pp];
        }
        idx = t;
        #pragma unroll
        for (int i = 0; i < 4; i++, idx += 256) {
            int ocp = idx >> 4, kk = idx & 15;
            Ws[kk * 68 + ocp] = w[(size_t)(oc0 + ocp) * Cp2 + k0 + kk];
        }
        __syncthreads();
        #pragma unroll
        for (int kk = 0; kk < 16; kk++) {
            float a4[4], b4[4];
            #pragma unroll
            for (int j = 0; j < 4; j++) a4[j] = Xs[kk * 64 + tx * 4 + j];
            #pragma unroll
            for (int i = 0; i < 4; i++) b4[i] = Ws[kk * 68 + ty * 4 + i];
            #pragma unroll
            for (int i = 0; i < 4; i++)
                #pragma unroll
                for (int j = 0; j < 4; j++)
                    acc[i][j] += b4[i] * a4[j];
        }
        __syncthreads();
    }
    float invW = 2.f / (float)(W - 1), invH = 2.f / (float)(H - 1);
    #pragma unroll
    for (int i = 0; i < 4; i++) {
        int oc = oc0 + ty * 4 + i;
        float cx = w[(size_t)oc * Cp2 + C];
        float cy = w[(size_t)oc * Cp2 + C + 1];
        float bb = bias[oc];
        #pragma unroll
        for (int j = 0; j < 4; j++) {
            int p = p0 + tx * 4 + j;
            float xg = -1.f + (float)(p % W) * invW;
            float yg = -1.f + (float)(p / W) * invH;
            o[(size_t)(b * OC + oc) * HW + p] = acc[i][j] + cx * xg + cy * yg + bb;
        }
    }
}

// blocks: L0 1024 (64 p x 4 oc x 4 b) | L1 512 (16x8x4) | L2 256 (4x16x4)
__global__ __launch_bounds__(256) void conv_all_kernel(
    const float* __restrict__ w1, const float* __restrict__ b1,
    const float* __restrict__ w2, const float* __restrict__ b2,
    const float* __restrict__ w3, const float* __restrict__ b3) {
    __shared__ float Xs[16 * 64];
    __shared__ float Ws[16 * 68];
    int id = blockIdx.x, t = threadIdx.x;
    if (id < 1024) {
        conv_body(g_pool0, w1, b1, g_conv0, 256, 256, 64, 64,
                  id / 256, id % 64, (id / 64) & 3, Xs, Ws, t);
    } else if (id < 1536) {
        id -= 1024;
        conv_body(g_pool1, w2, b2, g_conv1, 512, 512, 32, 32,
                  id / 128, id % 16, (id / 16) & 7, Xs, Ws, t);
    } else {
        id -= 1536;
        conv_body(g_pool2, w3, b3, g_conv2, 1024, 1024, 16, 16,
                  id / 64, id % 4, (id / 4) & 15, Xs, Ws, t);
    }
}

// ===================== launch 3: phi (fused resize + out2 + feats) =====================
DI float bilin(const float* __restrict__ sp, int S, int p) {
    int h = p >> 6, ww = p & 63;
    float sc = (float)S / 64.f;
    float fy = ((float)h + 0.5f) * sc - 0.5f; fy = fminf(fmaxf(fy, 0.f), (float)(S - 1));
    float fx = ((float)ww + 0.5f) * sc - 0.5f; fx = fminf(fmaxf(fx, 0.f), (float)(S - 1));
    int y0 = (int)fy, x0 = (int)fx;
    int y1 = min(y0 + 1, S - 1), x1 = min(x0 + 1, S - 1);
    float wy = fy - (float)y0, wx = fx - (float)x0;
    float v00 = sp[y0 * S + x0], v01 = sp[y0 * S + x1];
    float v10 = sp[y1 * S + x0], v11 = sp[y1 * S + x1];
    return (1.f - wy) * ((1.f - wx) * v00 + wx * v01) + wy * ((1.f - wx) * v10 + wx * v11);
}

DI float fetch2(int b, int ch, int p) {
    if (ch < 256)  return g_conv0[(((size_t)(b * 256 + ch)) << 12) + p];
    if (ch < 768)  return bilin(&g_conv1[(size_t)(b * 512 + ch - 256) * 1024], 32, p);
    return bilin(&g_conv2[(size_t)(b * 1024 + ch - 768) * 256], 16, p);
}

__global__ void phi_all_kernel(float* __restrict__ out2) {
    __shared__ float tile[32][33];
    int b = blockIdx.z, ch0 = blockIdx.x * 32, p0 = blockIdx.y * 32;
    int tx = threadIdx.x, ty = threadIdx.y;
    for (int i = ty; i < 32; i += 8) {
        int ch = ch0 + i, p = p0 + tx;
        float v = fetch2(b, ch, p);
        tile[i][tx] = v;
        if (ch < 896)
            out2[(((size_t)(b * 896 + ch)) << 12) + p] = v;
    }
    __syncthreads();
    for (int i = ty; i < 32; i += 8) {
        int p = p0 + i;
        float v = tile[tx][i];
        g_phi[(size_t)(b * 4096 + p) * NCH + ch0 + tx] = __float2bfloat16(v);
        float s = v * v;
        s += __shfl_xor_sync(FULLMASK, s, 16);
        s += __shfl_xor_sync(FULLMASK, s, 8);
        s += __shfl_xor_sync(FULLMASK, s, 4);
        s += __shfl_xor_sync(FULLMASK, s, 2);
        s += __shfl_xor_sync(FULLMASK, s, 1);
        if (tx == 0) atomicAdd(&g_feats[b * 4096 + p], s);
    }
}

// ===================== launch 4: distance GEMM (128x256, K-chunk 64) =====================
#define A_STRIDE 144
#define SA_BYTES (128*144)
#define SB_BYTES (256*144)
#define STAGE_BYTES (SA_BYTES+SB_BYTES)   // 55296
#define GEMM_SMEM (2*STAGE_BYTES)         // 110592
#define NKCHUNK 28

DI void gemm_load_chunk(uint32_t sbuf, int m0, int n0, int k0, int t) {
    uint32_t sA = sbuf, sB = sbuf + SA_BYTES;
    #pragma unroll
    for (int i = 0; i < 2; i++) {
        int idx = t + i * 512;
        int row = idx >> 3, seg = idx & 7;
        cpasync16(sA + row * A_STRIDE + seg * 16,
                  &g_phi[(size_t)(m0 + row) * NCH + k0 + seg * 8]);
    }
    #pragma unroll
    for (int i = 0; i < 4; i++) {
        int idx = t + i * 512;
        int row = idx >> 3, seg = idx & 7;
        cpasync16(sB + row * A_STRIDE + seg * 16,
                  &g_ct[(size_t)(n0 + row) * NCH + k0 + seg * 8]);
    }
    cp_commit();
}

__global__ __launch_bounds__(512, 1) void gemm_kernel() {
    extern __shared__ __align__(16) char smem[];
    const uint32_t sbase = smem_u32(smem);
    int t = threadIdx.x, lane = t & 31, wid = t >> 5;
    int wm = wid & 1, wn = wid >> 1;     // 2 x 8 warp grid; warp tile 64x32
    int m0 = blockIdx.x * 128, n0 = blockIdx.y * 256;

    float c[4][4][4];
    #pragma unroll
    for (int i = 0; i < 4; i++)
        #pragma unroll
        for (int j = 0; j < 4; j++)
            #pragma unroll
            for (int r = 0; r < 4; r++) c[i][j][r] = 0.f;

    const uint32_t a_row = wm * 64 + (lane & 15);
    const uint32_t a_base = a_row * A_STRIDE + ((lane >> 4) * 16);
    const uint32_t b_row = wn * 32 + ((lane >> 4) * 8) + (lane & 7);
    const uint32_t b_base = b_row * A_STRIDE + (((lane >> 3) & 1) * 16);

    gemm_load_chunk(sbase, m0, n0, 0, t);

    #pragma unroll 1
    for (int ck = 0; ck < NKCHUNK; ck++) {
        int buf = ck & 1;
        if (ck + 1 < NKCHUNK) {
            gemm_load_chunk(sbase + (buf ^ 1) * STAGE_BYTES, m0, n0, (ck + 1) * 64, t);
            cp_wait1();
        } else {
            cp_wait0();
        }
        __syncthreads();

        uint32_t sA = sbase + buf * STAGE_BYTES;
        uint32_t sB = sA + SA_BYTES;
        #pragma unroll
        for (int ks = 0; ks < 4; ks++) {
            uint32_t a[4][4];
            #pragma unroll
            for (int mi = 0; mi < 4; mi++)
                ldsm4(a[mi], sA + a_base + mi * (16 * A_STRIDE) + ks * 32);
            uint32_t bfr[2][4];
            #pragma unroll
            for (int np = 0; np < 2; np++)
                ldsm4(bfr[np], sB + b_base + np * (16 * A_STRIDE) + ks * 32);
            #pragma unroll
            for (int mi = 0; mi < 4; mi++)
                #pragma unroll
                for (int np = 0; np < 2; np++) {
                    mma16816(c[mi][np * 2 + 0], a[mi], bfr[np][0], bfr[np][1]);
                    mma16816(c[mi][np * 2 + 1], a[mi], bfr[np][2], bfr[np][3]);
                }
        }
        __syncthreads();
    }

    #pragma unroll
    for (int mi = 0; mi < 4; mi++) {
        int r0 = m0 + wm * 64 + mi * 16 + (lane >> 2);
        float f0 = g_feats[r0], f1 = g_feats[r0 + 8];
        #pragma unroll
        for (int ni = 0; ni < 4; ni++) {
            int cc = n0 + wn * 32 + ni * 8 + (lane & 3) * 2;
            float ce0 = g_cents[cc], ce1 = g_cents[cc + 1];
            float* dp = &g_dist2[(size_t)r0 * 4096 + cc];
            float2 v0 = { f0 + ce0 - 2.f * c[mi][ni][0], f0 + ce1 - 2.f * c[mi][ni][1] };
            float2 v1 = { f1 + ce0 - 2.f * c[mi][ni][2], f1 + ce1 - 2.f * c[mi][ni][3] };
            *reinterpret_cast<float2*>(dp) = v0;
            *reinterpret_cast<float2*>(dp + (size_t)8 * 4096) = v1;
        }
    }
}

// ===================== launch 5: top-200 per row =====================
__global__ __launch_bounds__(256) void topk_kernel(float* __restrict__ out) {
    __shared__ float keys[4096];
    __shared__ unsigned hist[256];
    __shared__ unsigned scan[256];
    __shared__ unsigned sh_want, sh_prefix;
    __shared__ unsigned cnt_lt;
    __shared__ float sel[256];

    int row = blockIdx.x;
    int t = threadIdx.x;
    int lane = t & 31;
    const float4* src4 = reinterpret_cast<const float4*>(&g_dist2[(size_t)row * 4096]);
    for (int i = t; i < 1024; i += 256) {
        float4 v = src4[i];
        keys[i * 4 + 0] = v.x; keys[i * 4 + 1] = v.y;
        keys[i * 4 + 2] = v.z; keys[i * 4 + 3] = v.w;
    }
    if (t == 0) { sh_want = NNEI; sh_prefix = 0; cnt_lt = 0; }
    __syncthreads();

    for (int pass = 0; pass < 4; pass++) {
        int shift = 24 - pass * 8;
        unsigned pfx = sh_prefix;
        unsigned want = sh_want;
        hist[t] = 0;
        __syncthreads();
        for (int i = t; i < 4096; i += 256) {
            unsigned u = __float_as_uint(keys[i]);
            bool ok = (pass == 0) || ((u >> (shift + 8)) == pfx);
            unsigned d = ok ? ((u >> shift) & 255u) : 0x100u;
            unsigned m = __match_any_sync(FULLMASK, d);
            if (ok && ((m & ((1u << lane) - 1u)) == 0))
                atomicAdd(&hist[d], (unsigned)__popc(m));
        }
        __syncthreads();
        scan[t] = hist[t];
        __syncthreads();
        for (int off = 1; off < 256; off <<= 1) {
            unsigned x = (t >= off) ? scan[t - off] : 0u;
            __syncthreads();
            scan[t] += x;
            __syncthreads();
        }
        unsigned below = (t == 0) ? 0u : scan[t - 1];
        if (below < want && want <= scan[t]) {
            sh_want = want - below;
            sh_prefix = (pfx << 8) | (unsigned)t;
        }
        __syncthreads();
    }

    unsigned Tb = sh_prefix;
    float Tf = __uint_as_float(Tb);
    for (int i = t; i < 4096; i += 256) {
        float v = keys[i];
        if (v < Tf) {
            unsigned pos = atomicAdd(&cnt_lt, 1u);
            sel[pos] = v;
        }
    }
    __syncthreads();
    unsigned base = cnt_lt;
    if ((unsigned)t >= base) sel[t] = (t < NNEI) ? Tf : __int_as_float(0x7f800000);
    __syncthreads();

    for (int k = 2; k <= 256; k <<= 1) {
        for (int j = k >> 1; j > 0; j >>= 1) {
            int ixj = t ^ j;
            if (ixj > t) {
                bool up = ((t & k) == 0);
                float a = sel[t], b = sel[ixj];
                if ((a > b) == up) { sel[t] = b; sel[ixj] = a; }
            }
            __syncthreads();
        }
    }

    if (t < NNEI) {
        int b = row >> 12, p = row & 4095;
        out[(((size_t)(b * NNEI + t)) << 12) + p] = sqrtf(sel[t]);
    }
}

// ===================== host launcher =====================
extern "C" void kernel_launch(void* const* d_in, const int* in_sizes, int n_in,
                              void* d_out, int out_size) {
    const float* p0 = (const float*)d_in[0];
    const float* p1 = (const float*)d_in[1];
    const float* p2 = (const float*)d_in[2];
    const float* w1 = (const float*)d_in[5];
    const float* b1 = (const float*)d_in[6];
    const float* w2 = (const float*)d_in[7];
    const float* b2 = (const float*)d_in[8];
    const float* w3 = (const float*)d_in[9];
    const float* b3 = (const float*)d_in[10];
    const float* Cm = (const float*)d_in[11];
    float* score = (float*)d_out;
    float* out2  = score + SCORE_ELEMS;

    static bool attr_set = false;
    if (!attr_set) {
        cudaFuncSetAttribute(gemm_kernel, cudaFuncAttributeMaxDynamicSharedMemorySize, GEMM_SMEM);
        attr_set = true;
    }

    prep_kernel<<<35920, 256>>>(p0, p1, p2, Cm);
    conv_all_kernel<<<1792, 256>>>(w1, b1, w2, b2, w3, b3);
    phi_all_kernel<<<dim3(NCH/32, 128, 4), dim3(32, 8)>>>(out2);
    gemm_kernel<<<dim3(M_TOT/128, NCENT/256), 512, GEMM_SMEM>>>();
    topk_kernel<<<M_TOT, 256>>>(score);
}

// round 5
// speedup vs baseline: 1.1638x; 1.0335x over previous
#include <cuda_runtime.h>
#include <cuda_bf16.h>
#include <cstdint>

#define DI __device__ __forceinline__
#define FULLMASK 0xFFFFFFFFu

// ===================== problem dims =====================
#define NBATCH 4
#define NPIX   4096
#define NCH    1792
#define NCENT  4096
#define M_TOT  (NBATCH*NPIX)
#define NNEI   200
#define SCORE_ELEMS (NBATCH*NNEI*NPIX)

// ===================== scratch =====================
__device__ float g_pool0[4u*256*64*64];
__device__ float g_pool1[4u*512*32*32];
__device__ float g_pool2[4u*1024*16*16];
__device__ float g_conv0[4u*256*64*64];
__device__ float g_conv1[4u*512*32*32];
__device__ float g_conv2[4u*1024*16*16];
__device__ __nv_bfloat16 g_phi[(size_t)M_TOT*NCH];
__device__ __nv_bfloat16 g_ct [(size_t)NCENT*NCH];
__device__ float g_feats[M_TOT];
__device__ float g_cents[NCENT];
__device__ float g_dist2[(size_t)M_TOT*NCENT];

// ===================== PTX helpers (sm_100 baseline ISA) =====================
DI uint32_t smem_u32(const void* p) {
    uint32_t a;
    asm("{ .reg .u64 t; cvta.to.shared.u64 t, %1; cvt.u32.u64 %0, t; }" : "=r"(a) : "l"(p));
    return a;
}
DI void ldsm4(uint32_t* r, uint32_t a) {
    asm volatile("ldmatrix.sync.aligned.m8n8.x4.shared.b16 {%0,%1,%2,%3}, [%4];"
        : "=r"(r[0]), "=r"(r[1]), "=r"(r[2]), "=r"(r[3]) : "r"(a));
}
DI void mma16816(float* c, const uint32_t* a, uint32_t b0, uint32_t b1) {
    asm volatile("mma.sync.aligned.m16n8k16.row.col.f32.bf16.bf16.f32 "
        "{%0,%1,%2,%3}, {%4,%5,%6,%7}, {%8,%9}, {%0,%1,%2,%3};"
        : "+f"(c[0]), "+f"(c[1]), "+f"(c[2]), "+f"(c[3])
        : "r"(a[0]), "r"(a[1]), "r"(a[2]), "r"(a[3]), "r"(b0), "r"(b1));
}
DI void cpasync16(uint32_t dst, const void* src) {
    asm volatile("cp.async.cg.shared.global [%0], [%1], 16;" :: "r"(dst), "l"(src) : "memory");
}
DI void cp_commit() { asm volatile("cp.async.commit_group;" ::: "memory"); }
DI void cp_wait1()  { asm volatile("cp.async.wait_group 1;" ::: "memory"); }
DI void cp_wait0()  { asm volatile("cp.async.wait_group 0;" ::: "memory"); }

// ===================== launch 1: prep mega-kernel =====================
DI void pool_body(const float* __restrict__ x, float* __restrict__ y,
                  int H, int W, int idx) {
    int w = idx % W;
    int h = (idx / W) % H;
    int bc = idx / (W * H);
    const float* p = x + (size_t)bc * H * W;
    float s = 0.f;
    #pragma unroll
    for (int dy = -1; dy <= 1; dy++) {
        int hh = h + dy;
        if (hh < 0 || hh >= H) continue;
        #pragma unroll
        for (int dx = -1; dx <= 1; dx++) {
            int ww = w + dx;
            if (ww < 0 || ww >= W) continue;
            s += p[hh * W + ww];
        }
    }
    y[idx] = s * (1.0f / 9.0f);
}

__global__ __launch_bounds__(256) void prep_kernel(
    const float* __restrict__ p0, const float* __restrict__ p1,
    const float* __restrict__ p2, const float* __restrict__ C) {
    int bb = blockIdx.x, t = threadIdx.x;
    if (bb < 16384) {
        pool_body(p0, g_pool0, 64, 64, bb * 256 + t);
    } else if (bb < 24576) {
        pool_body(p1, g_pool1, 32, 32, (bb - 16384) * 256 + t);
    } else if (bb < 28672) {
        pool_body(p2, g_pool2, 16, 16, (bb - 24576) * 256 + t);
    } else if (bb < 35840) {
        __shared__ float tile[32][33];
        int id = bb - 28672;
        int j0 = (id & 127) * 32, k0 = (id >> 7) * 32;
        int tx = t & 31, ty = t >> 5;
        for (int i = ty; i < 32; i += 8)
            tile[i][tx] = C[(size_t)(k0 + i) * 4096 + j0 + tx];
        __syncthreads();
        for (int i = ty; i < 32; i += 8)
            g_ct[(size_t)(j0 + i) * NCH + k0 + tx] = __float2bfloat16(tile[tx][i]);
    } else if (bb < 35856) {
        int j = (bb - 35840) * 256 + t;
        float s = 0.f;
        #pragma unroll 8
        for (int k = 0; k < NCH; k++) {
            float v = C[(size_t)k * 4096 + j];
            s += v * v;
        }
        g_cents[j] = s;
    } else {
        g_feats[(bb - 35856) * 256 + t] = 0.f;
    }
}

// ===================== launch 2: coord-conv all levels =====================
DI void conv_body(const float* __restrict__ x, const float* __restrict__ w,
                  const float* __restrict__ bias, float* __restrict__ o,
                  int C, int OC, int H, int W, int b, int px, int ocb,
                  float* Xs, float* Ws, int t) {
    int p0 = px * 64, oc0 = ocb * 64;
    int HW = H * W;
    int tx = t & 15, ty = t >> 4;
    int Cp2 = C + 2;
    float acc[4][4] = {};
    for (int k0 = 0; k0 < C; k0 += 16) {
        int idx = t;
        #pragma unroll
        for (int i = 0; i < 4; i++, idx += 256) {
            int kk = idx >> 6, pp = idx & 63;
            Xs[kk * 64 + pp] = x[(size_t)(b * C + k0 + kk) * HW + p0 + pp];
        }
        idx = t;
        #pragma unroll
        for (int i = 0; i < 4; i++, idx += 256) {
            int ocp = idx >> 4, kk = idx & 15;
            Ws[kk * 68 + ocp] = w[(size_t)(oc0 + ocp) * Cp2 + k0 + kk];
        }
        __syncthreads();
        #pragma unroll
        for (int kk = 0; kk < 16; kk++) {
            float a4[4], b4[4];
            #pragma unroll
            for (int j = 0; j < 4; j++) a4[j] = Xs[kk * 64 + tx * 4 + j];
            #pragma unroll
            for (int i = 0; i < 4; i++) b4[i] = Ws[kk * 68 + ty * 4 + i];
            #pragma unroll
            for (int i = 0; i < 4; i++)
                #pragma unroll
                for (int j = 0; j < 4; j++)
                    acc[i][j] += b4[i] * a4[j];
        }
        __syncthreads();
    }
    float invW = 2.f / (float)(W - 1), invH = 2.f / (float)(H - 1);
    #pragma unroll
    for (int i = 0; i < 4; i++) {
        int oc = oc0 + ty * 4 + i;
        float cx = w[(size_t)oc * Cp2 + C];
        float cy = w[(size_t)oc * Cp2 + C + 1];
        float bb = bias[oc];
        #pragma unroll
        for (int j = 0; j < 4; j++) {
            int p = p0 + tx * 4 + j;
            float xg = -1.f + (float)(p % W) * invW;
            float yg = -1.f + (float)(p / W) * invH;
            o[(size_t)(b * OC + oc) * HW + p] = acc[i][j] + cx * xg + cy * yg + bb;
        }
    }
}

__global__ __launch_bounds__(256) void conv_all_kernel(
    const float* __restrict__ w1, const float* __restrict__ b1,
    const float* __restrict__ w2, const float* __restrict__ b2,
    const float* __restrict__ w3, const float* __restrict__ b3) {
    __shared__ float Xs[16 * 64];
    __shared__ float Ws[16 * 68];
    int id = blockIdx.x, t = threadIdx.x;
    if (id < 1024) {
        conv_body(g_pool0, w1, b1, g_conv0, 256, 256, 64, 64,
                  id / 256, id % 64, (id / 64) & 3, Xs, Ws, t);
    } else if (id < 1536) {
        id -= 1024;
        conv_body(g_pool1, w2, b2, g_conv1, 512, 512, 32, 32,
                  id / 128, id % 16, (id / 16) & 7, Xs, Ws, t);
    } else {
        id -= 1536;
        conv_body(g_pool2, w3, b3, g_conv2, 1024, 1024, 16, 16,
                  id / 64, id % 4, (id / 4) & 15, Xs, Ws, t);
    }
}

// ===================== launch 3: phi (fused resize + out2 + feats) =====================
DI float bilin(const float* __restrict__ sp, int S, int p) {
    int h = p >> 6, ww = p & 63;
    float sc = (float)S / 64.f;
    float fy = ((float)h + 0.5f) * sc - 0.5f; fy = fminf(fmaxf(fy, 0.f), (float)(S - 1));
    float fx = ((float)ww + 0.5f) * sc - 0.5f; fx = fminf(fmaxf(fx, 0.f), (float)(S - 1));
    int y0 = (int)fy, x0 = (int)fx;
    int y1 = min(y0 + 1, S - 1), x1 = min(x0 + 1, S - 1);
    float wy = fy - (float)y0, wx = fx - (float)x0;
    float v00 = sp[y0 * S + x0], v01 = sp[y0 * S + x1];
    float v10 = sp[y1 * S + x0], v11 = sp[y1 * S + x1];
    return (1.f - wy) * ((1.f - wx) * v00 + wx * v01) + wy * ((1.f - wx) * v10 + wx * v11);
}

DI float fetch2(int b, int ch, int p) {
    if (ch < 256)  return g_conv0[(((size_t)(b * 256 + ch)) << 12) + p];
    if (ch < 768)  return bilin(&g_conv1[(size_t)(b * 512 + ch - 256) * 1024], 32, p);
    return bilin(&g_conv2[(size_t)(b * 1024 + ch - 768) * 256], 16, p);
}

__global__ void phi_all_kernel(float* __restrict__ out2) {
    __shared__ float tile[32][33];
    int b = blockIdx.z, ch0 = blockIdx.x * 32, p0 = blockIdx.y * 32;
    int tx = threadIdx.x, ty = threadIdx.y;
    for (int i = ty; i < 32; i += 8) {
        int ch = ch0 + i, p = p0 + tx;
        float v = fetch2(b, ch, p);
        tile[i][tx] = v;
        if (ch < 896)
            out2[(((size_t)(b * 896 + ch)) << 12) + p] = v;
    }
    __syncthreads();
    for (int i = ty; i < 32; i += 8) {
        int p = p0 + i;
        float v = tile[tx][i];
        g_phi[(size_t)(b * 4096 + p) * NCH + ch0 + tx] = __float2bfloat16(v);
        float s = v * v;
        s += __shfl_xor_sync(FULLMASK, s, 16);
        s += __shfl_xor_sync(FULLMASK, s, 8);
        s += __shfl_xor_sync(FULLMASK, s, 4);
        s += __shfl_xor_sync(FULLMASK, s, 2);
        s += __shfl_xor_sync(FULLMASK, s, 1);
        if (tx == 0) atomicAdd(&g_feats[b * 4096 + p], s);
    }
}

// ===================== launch 4: distance GEMM (128x256, K-chunk 64, 3-stage) =====================
#define A_STRIDE 144
#define SA_BYTES (128*144)
#define SB_BYTES (256*144)
#define STAGE_BYTES (SA_BYTES+SB_BYTES)   // 55296
#define NSTAGE 3
#define GEMM_SMEM (NSTAGE*STAGE_BYTES)    // 165888
#define NKCHUNK 28

DI void gemm_load_chunk(uint32_t sbuf, int m0, int n0, int k0, int t) {
    uint32_t sA = sbuf, sB = sbuf + SA_BYTES;
    #pragma unroll
    for (int i = 0; i < 2; i++) {
        int idx = t + i * 512;
        int row = idx >> 3, seg = idx & 7;
        cpasync16(sA + row * A_STRIDE + seg * 16,
                  &g_phi[(size_t)(m0 + row) * NCH + k0 + seg * 8]);
    }
    #pragma unroll
    for (int i = 0; i < 4; i++) {
        int idx = t + i * 512;
        int row = idx >> 3, seg = idx & 7;
        cpasync16(sB + row * A_STRIDE + seg * 16,
                  &g_ct[(size_t)(n0 + row) * NCH + k0 + seg * 8]);
    }
    cp_commit();
}

__global__ __launch_bounds__(512, 1) void gemm_kernel() {
    extern __shared__ __align__(16) char smem[];
    const uint32_t sbase = smem_u32(smem);
    int t = threadIdx.x, lane = t & 31, wid = t >> 5;
    int wm = wid & 1, wn = wid >> 1;     // 2 x 8 warp grid; warp tile 64x32
    int m0 = blockIdx.x * 128, n0 = blockIdx.y * 256;

    float c[4][4][4];
    #pragma unroll
    for (int i = 0; i < 4; i++)
        #pragma unroll
        for (int j = 0; j < 4; j++)
            #pragma unroll
            for (int r = 0; r < 4; r++) c[i][j][r] = 0.f;

    const uint32_t a_row = wm * 64 + (lane & 15);
    const uint32_t a_base = a_row * A_STRIDE + ((lane >> 4) * 16);
    const uint32_t b_row = wn * 32 + ((lane >> 4) * 8) + (lane & 7);
    const uint32_t b_base = b_row * A_STRIDE + (((lane >> 3) & 1) * 16);

    // prologue: stages 0 and 1 in flight
    gemm_load_chunk(sbase, m0, n0, 0, t);
    gemm_load_chunk(sbase + STAGE_BYTES, m0, n0, 64, t);

    int stage = 0;
    #pragma unroll 1
    for (int ck = 0; ck < NKCHUNK; ck++) {
        if (ck == NKCHUNK - 1) cp_wait0(); else cp_wait1();
        __syncthreads();
        // issue load for chunk ck+2 into the stage freed by chunk ck-1
        if (ck + 2 < NKCHUNK) {
            int ls = stage + 2; if (ls >= NSTAGE) ls -= NSTAGE;
            gemm_load_chunk(sbase + ls * STAGE_BYTES, m0, n0, (ck + 2) * 64, t);
        }
        uint32_t sA = sbase + stage * STAGE_BYTES;
        uint32_t sB = sA + SA_BYTES;
        #pragma unroll
        for (int ks = 0; ks < 4; ks++) {
            uint32_t a[4][4];
            #pragma unroll
            for (int mi = 0; mi < 4; mi++)
                ldsm4(a[mi], sA + a_base + mi * (16 * A_STRIDE) + ks * 32);
            uint32_t bfr[2][4];
            #pragma unroll
            for (int np = 0; np < 2; np++)
                ldsm4(bfr[np], sB + b_base + np * (16 * A_STRIDE) + ks * 32);
            #pragma unroll
            for (int mi = 0; mi < 4; mi++)
                #pragma unroll
                for (int np = 0; np < 2; np++) {
                    mma16816(c[mi][np * 2 + 0], a[mi], bfr[np][0], bfr[np][1]);
                    mma16816(c[mi][np * 2 + 1], a[mi], bfr[np][2], bfr[np][3]);
                }
        }
        if (++stage >= NSTAGE) stage = 0;
    }

    #pragma unroll
    for (int mi = 0; mi < 4; mi++) {
        int r0 = m0 + wm * 64 + mi * 16 + (lane >> 2);
        float f0 = g_feats[r0], f1 = g_feats[r0 + 8];
        #pragma unroll
        for (int ni = 0; ni < 4; ni++) {
            int cc = n0 + wn * 32 + ni * 8 + (lane & 3) * 2;
            float ce0 = g_cents[cc], ce1 = g_cents[cc + 1];
            float* dp = &g_dist2[(size_t)r0 * 4096 + cc];
            float2 v0 = { f0 + ce0 - 2.f * c[mi][ni][0], f0 + ce1 - 2.f * c[mi][ni][1] };
            float2 v1 = { f1 + ce0 - 2.f * c[mi][ni][2], f1 + ce1 - 2.f * c[mi][ni][3] };
            *reinterpret_cast<float2*>(dp) = v0;
            *reinterpret_cast<float2*>(dp + (size_t)8 * 4096) = v1;
        }
    }
}

// ===================== launch 5: top-200 per row =====================
__global__ __launch_bounds__(256) void topk_kernel(float* __restrict__ out) {
    __shared__ float keys[4096];
    __shared__ unsigned hist[256];
    __shared__ unsigned scan[256];
    __shared__ unsigned sh_want, sh_prefix;
    __shared__ unsigned cnt_lt;
    __shared__ float sel[256];

    int row = blockIdx.x;
    int t = threadIdx.x;
    int lane = t & 31;
    const float4* src4 = reinterpret_cast<const float4*>(&g_dist2[(size_t)row * 4096]);
    for (int i = t; i < 1024; i += 256) {
        float4 v = src4[i];
        keys[i * 4 + 0] = v.x; keys[i * 4 + 1] = v.y;
        keys[i * 4 + 2] = v.z; keys[i * 4 + 3] = v.w;
    }
    if (t == 0) { sh_want = NNEI; sh_prefix = 0; cnt_lt = 0; }
    __syncthreads();

    for (int pass = 0; pass < 4; pass++) {
        int shift = 24 - pass * 8;
        unsigned pfx = sh_prefix;
        unsigned want = sh_want;
        hist[t] = 0;
        __syncthreads();
        for (int i = t; i < 4096; i += 256) {
            unsigned u = __float_as_uint(keys[i]);
            bool ok = (pass == 0) || ((u >> (shift + 8)) == pfx);
            unsigned d = ok ? ((u >> shift) & 255u) : 0x100u;
            unsigned m = __match_any_sync(FULLMASK, d);
            if (ok && ((m & ((1u << lane) - 1u)) == 0))
                atomicAdd(&hist[d], (unsigned)__popc(m));
        }
        __syncthreads();
        // single-warp inclusive scan of the 256-bin histogram
        if (t < 32) {
            unsigned vals[8], tot = 0;
            #pragma unroll
            for (int i = 0; i < 8; i++) { vals[i] = hist[t * 8 + i]; tot += vals[i]; }
            unsigned run = tot;
            #pragma unroll
            for (int off = 1; off < 32; off <<= 1) {
                unsigned x = __shfl_up_sync(FULLMASK, run, off);
                if (t >= off) run += x;
            }
            unsigned acc = run - tot;
            #pragma unroll
            for (int i = 0; i < 8; i++) { acc += vals[i]; scan[t * 8 + i] = acc; }
        }
        __syncthreads();
        unsigned below = (t == 0) ? 0u : scan[t - 1];
        if (below < want && want <= scan[t]) {
            sh_want = want - below;
            sh_prefix = (pfx << 8) | (unsigned)t;
        }
        __syncthreads();
    }

    unsigned Tb = sh_prefix;
    float Tf = __uint_as_float(Tb);
    for (int i = t; i < 4096; i += 256) {
        float v = keys[i];
        if (v < Tf) {
            unsigned pos = atomicAdd(&cnt_lt, 1u);
            sel[pos] = v;
        }
    }
    __syncthreads();
    unsigned base = cnt_lt;
    if ((unsigned)t >= base) sel[t] = (t < NNEI) ? Tf : __int_as_float(0x7f800000);
    __syncthreads();

    for (int k = 2; k <= 256; k <<= 1) {
        for (int j = k >> 1; j > 0; j >>= 1) {
            int ixj = t ^ j;
            if (ixj > t) {
                bool up = ((t & k) == 0);
                float a = sel[t], b = sel[ixj];
                if ((a > b) == up) { sel[t] = b; sel[ixj] = a; }
            }
            __syncthreads();
        }
    }

    if (t < NNEI) {
        int b = row >> 12, p = row & 4095;
        out[(((size_t)(b * NNEI + t)) << 12) + p] = sqrtf(sel[t]);
    }
}

// ===================== host launcher =====================
extern "C" void kernel_launch(void* const* d_in, const int* in_sizes, int n_in,
                              void* d_out, int out_size) {
    const float* p0 = (const float*)d_in[0];
    const float* p1 = (const float*)d_in[1];
    const float* p2 = (const float*)d_in[2];
    const float* w1 = (const float*)d_in[5];
    const float* b1 = (const float*)d_in[6];
    const float* w2 = (const float*)d_in[7];
    const float* b2 = (const float*)d_in[8];
    const float* w3 = (const float*)d_in[9];
    const float* b3 = (const float*)d_in[10];
    const float* Cm = (const float*)d_in[11];
    float* score = (float*)d_out;
    float* out2  = score + SCORE_ELEMS;

    static bool attr_set = false;
    if (!attr_set) {
        cudaFuncSetAttribute(gemm_kernel, cudaFuncAttributeMaxDynamicSharedMemorySize, GEMM_SMEM);
        attr_set = true;
    }

    prep_kernel<<<35920, 256>>>(p0, p1, p2, Cm);
    conv_all_kernel<<<1792, 256>>>(w1, b1, w2, b2, w3, b3);
    phi_all_kernel<<<dim3(NCH/32, 128, 4), dim3(32, 8)>>>(out2);
    gemm_kernel<<<dim3(M_TOT/128, NCENT/256), 512, GEMM_SMEM>>>();
    topk_kernel<<<M_TOT, 256>>>(score);
}

// round 6
// speedup vs baseline: 1.2158x; 1.0446x over previous
#include <cuda_runtime.h>
#include <cuda_bf16.h>
#include <cstdint>

#define DI __device__ __forceinline__
#define FULLMASK 0xFFFFFFFFu

// ===================== problem dims =====================
#define NBATCH 4
#define NPIX   4096
#define NCH    1792
#define NCENT  4096
#define M_TOT  (NBATCH*NPIX)
#define NNEI   200
#define SCORE_ELEMS (NBATCH*NNEI*NPIX)

// ===================== scratch =====================
__device__ float g_pool0[4u*256*64*64];
__device__ float g_pool1[4u*512*32*32];
__device__ float g_pool2[4u*1024*16*16];
__device__ float g_conv0[4u*256*64*64];
__device__ float g_conv1[4u*512*32*32];
__device__ float g_conv2[4u*1024*16*16];
__device__ __nv_bfloat16 g_phi[(size_t)M_TOT*NCH];
__device__ __nv_bfloat16 g_ct [(size_t)NCENT*NCH];
__device__ float g_feats[M_TOT];
__device__ float g_cents[NCENT];
__device__ float g_dist2[(size_t)M_TOT*NCENT];

// ===================== PTX helpers (sm_100 baseline ISA) =====================
DI uint32_t smem_u32(const void* p) {
    uint32_t a;
    asm("{ .reg .u64 t; cvta.to.shared.u64 t, %1; cvt.u32.u64 %0, t; }" : "=r"(a) : "l"(p));
    return a;
}
DI void ldsm4(uint32_t* r, uint32_t a) {
    asm volatile("ldmatrix.sync.aligned.m8n8.x4.shared.b16 {%0,%1,%2,%3}, [%4];"
        : "=r"(r[0]), "=r"(r[1]), "=r"(r[2]), "=r"(r[3]) : "r"(a));
}
DI void mma16816(float* c, const uint32_t* a, uint32_t b0, uint32_t b1) {
    asm volatile("mma.sync.aligned.m16n8k16.row.col.f32.bf16.bf16.f32 "
        "{%0,%1,%2,%3}, {%4,%5,%6,%7}, {%8,%9}, {%0,%1,%2,%3};"
        : "+f"(c[0]), "+f"(c[1]), "+f"(c[2]), "+f"(c[3])
        : "r"(a[0]), "r"(a[1]), "r"(a[2]), "r"(a[3]), "r"(b0), "r"(b1));
}
DI void cpasync16(uint32_t dst, const void* src) {
    asm volatile("cp.async.cg.shared.global [%0], [%1], 16;" :: "r"(dst), "l"(src) : "memory");
}
DI void cp_commit() { asm volatile("cp.async.commit_group;" ::: "memory"); }
DI void cp_wait1()  { asm volatile("cp.async.wait_group 1;" ::: "memory"); }
DI void cp_wait0()  { asm volatile("cp.async.wait_group 0;" ::: "memory"); }

// ===================== launch 1: prep mega-kernel =====================
// blocks: [0,16384) pool0 | [16384,24576) pool1 | [24576,28672) pool2 |
//         [28672,35840) C-transpose | [35840,35968) cents(8-way ksplit x16) | [35968,36032) zero feats
DI void pool_body(const float* __restrict__ x, float* __restrict__ y,
                  int H, int W, int idx) {
    int w = idx % W;
    int h = (idx / W) % H;
    int bc = idx / (W * H);
    const float* p = x + (size_t)bc * H * W;
    float s = 0.f;
    #pragma unroll
    for (int dy = -1; dy <= 1; dy++) {
        int hh = h + dy;
        if (hh < 0 || hh >= H) continue;
        #pragma unroll
        for (int dx = -1; dx <= 1; dx++) {
            int ww = w + dx;
            if (ww < 0 || ww >= W) continue;
            s += p[hh * W + ww];
        }
    }
    y[idx] = s * (1.0f / 9.0f);
}

__global__ __launch_bounds__(256) void prep_kernel(
    const float* __restrict__ p0, const float* __restrict__ p1,
    const float* __restrict__ p2, const float* __restrict__ C) {
    int bb = blockIdx.x, t = threadIdx.x;
    if (bb < 16384) {
        pool_body(p0, g_pool0, 64, 64, bb * 256 + t);
    } else if (bb < 24576) {
        pool_body(p1, g_pool1, 32, 32, (bb - 16384) * 256 + t);
    } else if (bb < 28672) {
        pool_body(p2, g_pool2, 16, 16, (bb - 24576) * 256 + t);
    } else if (bb < 35840) {
        __shared__ float tile[32][33];
        int id = bb - 28672;
        int j0 = (id & 127) * 32, k0 = (id >> 7) * 32;
        int tx = t & 31, ty = t >> 5;
        for (int i = ty; i < 32; i += 8)
            tile[i][tx] = C[(size_t)(k0 + i) * 4096 + j0 + tx];
        __syncthreads();
        for (int i = ty; i < 32; i += 8)
            g_ct[(size_t)(j0 + i) * NCH + k0 + tx] = __float2bfloat16(tile[tx][i]);
    } else if (bb < 35968) {
        // cents: 128 blocks; each block: 32 j-cols, 8 k-splits of 224
        __shared__ float red[256];
        int id = bb - 35840;
        int j = (id & 127) * 32 + (t & 31);
        int kp = t >> 5;            // 0..7
        float s = 0.f;
        int kbeg = kp * 224, kend = kbeg + 224;
        for (int k = kbeg; k < kend; k++) {
            float v = C[(size_t)k * 4096 + j];
            s += v * v;
        }
        red[t] = s;
        __syncthreads();
        if (t < 32) {
            float acc = red[t];
            #pragma unroll
            for (int i = 1; i < 8; i++) acc += red[t + i * 32];
            g_cents[j] = acc;
        }
    } else {
        g_feats[(bb - 35968) * 256 + t] = 0.f;
    }
}

// ===================== launch 2: coord-conv (128oc x 64px tile, 8x4/thread) =====================
DI void conv_body(const float* __restrict__ x, const float* __restrict__ w,
                  const float* __restrict__ bias, float* __restrict__ o,
                  int C, int OC, int H, int W, int b, int px, int ocb,
                  float* Xs, float* Ws, int t) {
    int p0 = px * 64, oc0 = ocb * 128;
    int HW = H * W;
    int tx = t & 15, ty = t >> 4;
    int Cp2 = C + 2;
    float acc[8][4] = {};
    for (int k0 = 0; k0 < C; k0 += 16) {
        int idx = t;
        #pragma unroll
        for (int i = 0; i < 4; i++, idx += 256) {
            int kk = idx >> 6, pp = idx & 63;
            Xs[kk * 64 + pp] = x[(size_t)(b * C + k0 + kk) * HW + p0 + pp];
        }
        idx = t;
        #pragma unroll
        for (int i = 0; i < 8; i++, idx += 256) {
            int ocp = idx >> 4, kk = idx & 15;
            Ws[kk * 132 + ocp] = w[(size_t)(oc0 + ocp) * Cp2 + k0 + kk];
        }
        __syncthreads();
        #pragma unroll
        for (int kk = 0; kk < 16; kk++) {
            float4 a4 = *reinterpret_cast<const float4*>(&Xs[kk * 64 + tx * 4]);
            float4 b0 = *reinterpret_cast<const float4*>(&Ws[kk * 132 + ty * 8]);
            float4 b1 = *reinterpret_cast<const float4*>(&Ws[kk * 132 + ty * 8 + 4]);
            float av[4] = { a4.x, a4.y, a4.z, a4.w };
            float bv[8] = { b0.x, b0.y, b0.z, b0.w, b1.x, b1.y, b1.z, b1.w };
            #pragma unroll
            for (int i = 0; i < 8; i++)
                #pragma unroll
                for (int j = 0; j < 4; j++)
                    acc[i][j] += bv[i] * av[j];
        }
        __syncthreads();
    }
    float invW = 2.f / (float)(W - 1), invH = 2.f / (float)(H - 1);
    #pragma unroll
    for (int i = 0; i < 8; i++) {
        int oc = oc0 + ty * 8 + i;
        float cx = w[(size_t)oc * Cp2 + C];
        float cy = w[(size_t)oc * Cp2 + C + 1];
        float bb = bias[oc];
        #pragma unroll
        for (int j = 0; j < 4; j++) {
            int p = p0 + tx * 4 + j;
            float xg = -1.f + (float)(p % W) * invW;
            float yg = -1.f + (float)(p / W) * invH;
            o[(size_t)(b * OC + oc) * HW + p] = acc[i][j] + cx * xg + cy * yg + bb;
        }
    }
}

// blocks: L0 512 (4b x 64px x 2oc) | L1 256 (4 x 16 x 4) | L2 128 (4 x 4 x 8)
__global__ __launch_bounds__(256) void conv_all_kernel(
    const float* __restrict__ w1, const float* __restrict__ b1,
    const float* __restrict__ w2, const float* __restrict__ b2,
    const float* __restrict__ w3, const float* __restrict__ b3) {
    __shared__ float Xs[16 * 64];
    __shared__ float Ws[16 * 132];
    int id = blockIdx.x, t = threadIdx.x;
    if (id < 512) {
        int b = id >> 7, rem = id & 127;
        conv_body(g_pool0, w1, b1, g_conv0, 256, 256, 64, 64,
                  b, rem & 63, rem >> 6, Xs, Ws, t);
    } else if (id < 768) {
        int v = id - 512;
        int b = v >> 6, rem = v & 63;
        conv_body(g_pool1, w2, b2, g_conv1, 512, 512, 32, 32,
                  b, rem & 15, rem >> 4, Xs, Ws, t);
    } else {
        int v = id - 768;
        int b = v >> 5, rem = v & 31;
        conv_body(g_pool2, w3, b3, g_conv2, 1024, 1024, 16, 16,
                  b, rem & 3, rem >> 2, Xs, Ws, t);
    }
}

// ===================== launch 3: phi (fused resize + out2 + feats) =====================
DI float bilin(const float* __restrict__ sp, int S, int p) {
    int h = p >> 6, ww = p & 63;
    float sc = (float)S / 64.f;
    float fy = ((float)h + 0.5f) * sc - 0.5f; fy = fminf(fmaxf(fy, 0.f), (float)(S - 1));
    float fx = ((float)ww + 0.5f) * sc - 0.5f; fx = fminf(fmaxf(fx, 0.f), (float)(S - 1));
    int y0 = (int)fy, x0 = (int)fx;
    int y1 = min(y0 + 1, S - 1), x1 = min(x0 + 1, S - 1);
    float wy = fy - (float)y0, wx = fx - (float)x0;
    float v00 = sp[y0 * S + x0], v01 = sp[y0 * S + x1];
    float v10 = sp[y1 * S + x0], v11 = sp[y1 * S + x1];
    return (1.f - wy) * ((1.f - wx) * v00 + wx * v01) + wy * ((1.f - wx) * v10 + wx * v11);
}

DI float fetch2(int b, int ch, int p) {
    if (ch < 256)  return g_conv0[(((size_t)(b * 256 + ch)) << 12) + p];
    if (ch < 768)  return bilin(&g_conv1[(size_t)(b * 512 + ch - 256) * 1024], 32, p);
    return bilin(&g_conv2[(size_t)(b * 1024 + ch - 768) * 256], 16, p);
}

__global__ void phi_all_kernel(float* __restrict__ out2) {
    __shared__ float tile[32][33];
    int b = blockIdx.z, ch0 = blockIdx.x * 32, p0 = blockIdx.y * 32;
    int tx = threadIdx.x, ty = threadIdx.y;
    for (int i = ty; i < 32; i += 8) {
        int ch = ch0 + i, p = p0 + tx;
        float v = fetch2(b, ch, p);
        tile[i][tx] = v;
        if (ch < 896)
            out2[(((size_t)(b * 896 + ch)) << 12) + p] = v;
    }
    __syncthreads();
    for (int i = ty; i < 32; i += 8) {
        int p = p0 + i;
        float v = tile[tx][i];
        g_phi[(size_t)(b * 4096 + p) * NCH + ch0 + tx] = __float2bfloat16(v);
        float s = v * v;
        s += __shfl_xor_sync(FULLMASK, s, 16);
        s += __shfl_xor_sync(FULLMASK, s, 8);
        s += __shfl_xor_sync(FULLMASK, s, 4);
        s += __shfl_xor_sync(FULLMASK, s, 2);
        s += __shfl_xor_sync(FULLMASK, s, 1);
        if (tx == 0) atomicAdd(&g_feats[b * 4096 + p], s);
    }
}

// ===================== launch 4: distance GEMM =====================
// CTA 128x256, 256 threads (8 warps 2x4), warp tile 64x64, K-chunk 64, 3-stage cp.async
#define A_STRIDE 144
#define SA_BYTES (128*144)
#define SB_BYTES (256*144)
#define STAGE_BYTES (SA_BYTES+SB_BYTES)   // 55296
#define NSTAGE 3
#define GEMM_SMEM (NSTAGE*STAGE_BYTES)    // 165888
#define NKCHUNK 28

DI void gemm_load_chunk(uint32_t sbuf, int m0, int n0, int k0, int t) {
    uint32_t sA = sbuf, sB = sbuf + SA_BYTES;
    #pragma unroll
    for (int i = 0; i < 4; i++) {
        int idx = t + i * 256;
        int row = idx >> 3, seg = idx & 7;
        cpasync16(sA + row * A_STRIDE + seg * 16,
                  &g_phi[(size_t)(m0 + row) * NCH + k0 + seg * 8]);
    }
    #pragma unroll
    for (int i = 0; i < 8; i++) {
        int idx = t + i * 256;
        int row = idx >> 3, seg = idx & 7;
        cpasync16(sB + row * A_STRIDE + seg * 16,
                  &g_ct[(size_t)(n0 + row) * NCH + k0 + seg * 8]);
    }
    cp_commit();
}

__global__ __launch_bounds__(256, 1) void gemm_kernel() {
    extern __shared__ __align__(16) char smem[];
    const uint32_t sbase = smem_u32(smem);
    int t = threadIdx.x, lane = t & 31, wid = t >> 5;
    int wm = wid & 1, wn = wid >> 1;     // 2 x 4 warp grid; warp tile 64x64
    int m0 = blockIdx.x * 128, n0 = blockIdx.y * 256;

    float c[4][8][4];
    #pragma unroll
    for (int i = 0; i < 4; i++)
        #pragma unroll
        for (int j = 0; j < 8; j++)
            #pragma unroll
            for (int r = 0; r < 4; r++) c[i][j][r] = 0.f;

    const uint32_t a_row = wm * 64 + (lane & 15);
    const uint32_t a_base = a_row * A_STRIDE + ((lane >> 4) * 16);
    const uint32_t b_row = wn * 64 + ((lane >> 4) * 8) + (lane & 7);
    const uint32_t b_base = b_row * A_STRIDE + (((lane >> 3) & 1) * 16);

    gemm_load_chunk(sbase, m0, n0, 0, t);
    gemm_load_chunk(sbase + STAGE_BYTES, m0, n0, 64, t);

    int stage = 0;
    #pragma unroll 1
    for (int ck = 0; ck < NKCHUNK; ck++) {
        if (ck == NKCHUNK - 1) cp_wait0(); else cp_wait1();
        __syncthreads();
        if (ck + 2 < NKCHUNK) {
            int ls = stage + 2; if (ls >= NSTAGE) ls -= NSTAGE;
            gemm_load_chunk(sbase + ls * STAGE_BYTES, m0, n0, (ck + 2) * 64, t);
        }
        uint32_t sA = sbase + stage * STAGE_BYTES;
        uint32_t sB = sA + SA_BYTES;
        #pragma unroll
        for (int ks = 0; ks < 4; ks++) {
            uint32_t a[4][4];
            #pragma unroll
            for (int mi = 0; mi < 4; mi++)
                ldsm4(a[mi], sA + a_base + mi * (16 * A_STRIDE) + ks * 32);
            uint32_t bfr[4][4];
            #pragma unroll
            for (int np = 0; np < 4; np++)
                ldsm4(bfr[np], sB + b_base + np * (16 * A_STRIDE) + ks * 32);
            #pragma unroll
            for (int mi = 0; mi < 4; mi++)
                #pragma unroll
                for (int np = 0; np < 4; np++) {
                    mma16816(c[mi][np * 2 + 0], a[mi], bfr[np][0], bfr[np][1]);
                    mma16816(c[mi][np * 2 + 1], a[mi], bfr[np][2], bfr[np][3]);
                }
        }
        if (++stage >= NSTAGE) stage = 0;
    }

    #pragma unroll
    for (int mi = 0; mi < 4; mi++) {
        int r0 = m0 + wm * 64 + mi * 16 + (lane >> 2);
        float f0 = g_feats[r0], f1 = g_feats[r0 + 8];
        #pragma unroll
        for (int ni = 0; ni < 8; ni++) {
            int cc = n0 + wn * 64 + ni * 8 + (lane & 3) * 2;
            float ce0 = g_cents[cc], ce1 = g_cents[cc + 1];
            float* dp = &g_dist2[(size_t)r0 * 4096 + cc];
            float2 v0 = { f0 + ce0 - 2.f * c[mi][ni][0], f0 + ce1 - 2.f * c[mi][ni][1] };
            float2 v1 = { f1 + ce0 - 2.f * c[mi][ni][2], f1 + ce1 - 2.f * c[mi][ni][3] };
            *reinterpret_cast<float2*>(dp) = v0;
            *reinterpret_cast<float2*>(dp + (size_t)8 * 4096) = v1;
        }
    }
}

// ===================== launch 5: top-200 per row =====================
__global__ __launch_bounds__(256) void topk_kernel(float* __restrict__ out) {
    __shared__ float keys[4096];
    __shared__ unsigned hist[256];
    __shared__ unsigned scan[256];
    __shared__ unsigned sh_want, sh_prefix;
    __shared__ unsigned cnt_lt;
    __shared__ float sel[256];

    int row = blockIdx.x;
    int t = threadIdx.x;
    int lane = t & 31;
    const float4* src4 = reinterpret_cast<const float4*>(&g_dist2[(size_t)row * 4096]);
    for (int i = t; i < 1024; i += 256) {
        float4 v = src4[i];
        keys[i * 4 + 0] = v.x; keys[i * 4 + 1] = v.y;
        keys[i * 4 + 2] = v.z; keys[i * 4 + 3] = v.w;
    }
    if (t == 0) { sh_want = NNEI; sh_prefix = 0; cnt_lt = 0; }
    __syncthreads();

    for (int pass = 0; pass < 4; pass++) {
        int shift = 24 - pass * 8;
        unsigned pfx = sh_prefix;
        unsigned want = sh_want;
        hist[t] = 0;
        __syncthreads();
        for (int i = t; i < 4096; i += 256) {
            unsigned u = __float_as_uint(keys[i]);
            bool ok = (pass == 0) || ((u >> (shift + 8)) == pfx);
            unsigned d = ok ? ((u >> shift) & 255u) : 0x100u;
            unsigned m = __match_any_sync(FULLMASK, d);
            if (ok && ((m & ((1u << lane) - 1u)) == 0))
                atomicAdd(&hist[d], (unsigned)__popc(m));
        }
        __syncthreads();
        if (t < 32) {
            unsigned vals[8], tot = 0;
            #pragma unroll
            for (int i = 0; i < 8; i++) { vals[i] = hist[t * 8 + i]; tot += vals[i]; }
            unsigned run = tot;
            #pragma unroll
            for (int off = 1; off < 32; off <<= 1) {
                unsigned x = __shfl_up_sync(FULLMASK, run, off);
                if (t >= off) run += x;
            }
            unsigned acc = run - tot;
            #pragma unroll
            for (int i = 0; i < 8; i++) { acc += vals[i]; scan[t * 8 + i] = acc; }
        }
        __syncthreads();
        unsigned below = (t == 0) ? 0u : scan[t - 1];
        if (below < want && want <= scan[t]) {
            sh_want = want - below;
            sh_prefix = (pfx << 8) | (unsigned)t;
        }
        __syncthreads();
    }

    unsigned Tb = sh_prefix;
    float Tf = __uint_as_float(Tb);
    for (int i = t; i < 4096; i += 256) {
        float v = keys[i];
        if (v < Tf) {
            unsigned pos = atomicAdd(&cnt_lt, 1u);
            sel[pos] = v;
        }
    }
    __syncthreads();
    unsigned base = cnt_lt;
    if ((unsigned)t >= base) sel[t] = (t < NNEI) ? Tf : __int_as_float(0x7f800000);
    __syncthreads();

    for (int k = 2; k <= 256; k <<= 1) {
        for (int j = k >> 1; j > 0; j >>= 1) {
            int ixj = t ^ j;
            if (ixj > t) {
                bool up = ((t & k) == 0);
                float a = sel[t], b = sel[ixj];
                if ((a > b) == up) { sel[t] = b; sel[ixj] = a; }
            }
            __syncthreads();
        }
    }

    if (t < NNEI) {
        int b = row >> 12, p = row & 4095;
        out[(((size_t)(b * NNEI + t)) << 12) + p] = sqrtf(sel[t]);
    }
}

// ===================== host launcher =====================
extern "C" void kernel_launch(void* const* d_in, const int* in_sizes, int n_in,
                              void* d_out, int out_size) {
    const float* p0 = (const float*)d_in[0];
    const float* p1 = (const float*)d_in[1];
    const float* p2 = (const float*)d_in[2];
    const float* w1 = (const float*)d_in[5];
    const float* b1 = (const float*)d_in[6];
    const float* w2 = (const float*)d_in[7];
    const float* b2 = (const float*)d_in[8];
    const float* w3 = (const float*)d_in[9];
    const float* b3 = (const float*)d_in[10];
    const float* Cm = (const float*)d_in[11];
    float* score = (float*)d_out;
    float* out2  = score + SCORE_ELEMS;

    static bool attr_set = false;
    if (!attr_set) {
        cudaFuncSetAttribute(gemm_kernel, cudaFuncAttributeMaxDynamicSharedMemorySize, GEMM_SMEM);
        attr_set = true;
    }

    prep_kernel<<<36032, 256>>>(p0, p1, p2, Cm);
    conv_all_kernel<<<896, 256>>>(w1, b1, w2, b2, w3, b3);
    phi_all_kernel<<<dim3(NCH/32, 128, 4), dim3(32, 8)>>>(out2);
    gemm_kernel<<<dim3(M_TOT/128, NCENT/256), 256, GEMM_SMEM>>>();
    topk_kernel<<<M_TOT, 256>>>(score);
}

// round 7
// speedup vs baseline: 1.2915x; 1.0623x over previous
#include <cuda_runtime.h>
#include <cuda_bf16.h>
#include <cstdint>

#define DI __device__ __forceinline__
#define FULLMASK 0xFFFFFFFFu

// ===================== problem dims =====================
#define NBATCH 4
#define NPIX   4096
#define NCH    1792
#define NCENT  4096
#define M_TOT  (NBATCH*NPIX)
#define NNEI   200
#define SCORE_ELEMS (NBATCH*NNEI*NPIX)

// ===================== scratch =====================
__device__ float g_pool0[4u*256*64*64];
__device__ float g_pool1[4u*512*32*32];
__device__ float g_pool2[4u*1024*16*16];
__device__ float g_conv0[4u*256*64*64];
__device__ float g_conv1[4u*512*32*32];
__device__ float g_conv2[4u*1024*16*16];
__device__ __nv_bfloat16 g_phi[(size_t)M_TOT*NCH];
__device__ __nv_bfloat16 g_ct [(size_t)NCENT*NCH];
__device__ float g_feats[M_TOT];
__device__ float g_cents[NCENT];
__device__ float g_dist2[(size_t)M_TOT*NCENT];

// ===================== PTX helpers (sm_100 baseline ISA) =====================
DI uint32_t smem_u32(const void* p) {
    uint32_t a;
    asm("{ .reg .u64 t; cvta.to.shared.u64 t, %1; cvt.u32.u64 %0, t; }" : "=r"(a) : "l"(p));
    return a;
}
DI void ldsm4(uint32_t* r, uint32_t a) {
    asm volatile("ldmatrix.sync.aligned.m8n8.x4.shared.b16 {%0,%1,%2,%3}, [%4];"
        : "=r"(r[0]), "=r"(r[1]), "=r"(r[2]), "=r"(r[3]) : "r"(a));
}
DI void mma16816(float* c, const uint32_t* a, uint32_t b0, uint32_t b1) {
    asm volatile("mma.sync.aligned.m16n8k16.row.col.f32.bf16.bf16.f32 "
        "{%0,%1,%2,%3}, {%4,%5,%6,%7}, {%8,%9}, {%0,%1,%2,%3};"
        : "+f"(c[0]), "+f"(c[1]), "+f"(c[2]), "+f"(c[3])
        : "r"(a[0]), "r"(a[1]), "r"(a[2]), "r"(a[3]), "r"(b0), "r"(b1));
}
DI void cpasync16(uint32_t dst, const void* src) {
    asm volatile("cp.async.cg.shared.global [%0], [%1], 16;" :: "r"(dst), "l"(src) : "memory");
}
DI void cp_commit() { asm volatile("cp.async.commit_group;" ::: "memory"); }
DI void cp_wait1()  { asm volatile("cp.async.wait_group 1;" ::: "memory"); }
DI void cp_wait0()  { asm volatile("cp.async.wait_group 0;" ::: "memory"); }

// ===================== launch 1: prep mega-kernel =====================
DI void pool_body(const float* __restrict__ x, float* __restrict__ y,
                  int H, int W, int idx) {
    int w = idx % W;
    int h = (idx / W) % H;
    int bc = idx / (W * H);
    const float* p = x + (size_t)bc * H * W;
    float s = 0.f;
    #pragma unroll
    for (int dy = -1; dy <= 1; dy++) {
        int hh = h + dy;
        if (hh < 0 || hh >= H) continue;
        #pragma unroll
        for (int dx = -1; dx <= 1; dx++) {
            int ww = w + dx;
            if (ww < 0 || ww >= W) continue;
            s += p[hh * W + ww];
        }
    }
    y[idx] = s * (1.0f / 9.0f);
}

__global__ __launch_bounds__(256) void prep_kernel(
    const float* __restrict__ p0, const float* __restrict__ p1,
    const float* __restrict__ p2, const float* __restrict__ C) {
    int bb = blockIdx.x, t = threadIdx.x;
    if (bb < 16384) {
        pool_body(p0, g_pool0, 64, 64, bb * 256 + t);
    } else if (bb < 24576) {
        pool_body(p1, g_pool1, 32, 32, (bb - 16384) * 256 + t);
    } else if (bb < 28672) {
        pool_body(p2, g_pool2, 16, 16, (bb - 24576) * 256 + t);
    } else if (bb < 35840) {
        __shared__ float tile[32][33];
        int id = bb - 28672;
        int j0 = (id & 127) * 32, k0 = (id >> 7) * 32;
        int tx = t & 31, ty = t >> 5;
        for (int i = ty; i < 32; i += 8)
            tile[i][tx] = C[(size_t)(k0 + i) * 4096 + j0 + tx];
        __syncthreads();
        for (int i = ty; i < 32; i += 8)
            g_ct[(size_t)(j0 + i) * NCH + k0 + tx] = __float2bfloat16(tile[tx][i]);
    } else if (bb < 35968) {
        __shared__ float red[256];
        int id = bb - 35840;
        int j = (id & 127) * 32 + (t & 31);
        int kp = t >> 5;
        float s = 0.f;
        int kbeg = kp * 224, kend = kbeg + 224;
        for (int k = kbeg; k < kend; k++) {
            float v = C[(size_t)k * 4096 + j];
            s += v * v;
        }
        red[t] = s;
        __syncthreads();
        if (t < 32) {
            float acc = red[t];
            #pragma unroll
            for (int i = 1; i < 8; i++) acc += red[t + i * 32];
            g_cents[j] = acc;
        }
    } else {
        g_feats[(bb - 35968) * 256 + t] = 0.f;
    }
}

// ===================== launch 2: coord-conv (128oc x 64px tile, 8x4/thread) =====================
DI void conv_body(const float* __restrict__ x, const float* __restrict__ w,
                  const float* __restrict__ bias, float* __restrict__ o,
                  int C, int OC, int H, int W, int b, int px, int ocb,
                  float* Xs, float* Ws, int t) {
    int p0 = px * 64, oc0 = ocb * 128;
    int HW = H * W;
    int tx = t & 15, ty = t >> 4;
    int Cp2 = C + 2;
    float acc[8][4] = {};
    for (int k0 = 0; k0 < C; k0 += 16) {
        int idx = t;
        #pragma unroll
        for (int i = 0; i < 4; i++, idx += 256) {
            int kk = idx >> 6, pp = idx & 63;
            Xs[kk * 64 + pp] = x[(size_t)(b * C + k0 + kk) * HW + p0 + pp];
        }
        idx = t;
        #pragma unroll
        for (int i = 0; i < 8; i++, idx += 256) {
            int ocp = idx >> 4, kk = idx & 15;
            Ws[kk * 132 + ocp] = w[(size_t)(oc0 + ocp) * Cp2 + k0 + kk];
        }
        __syncthreads();
        #pragma unroll
        for (int kk = 0; kk < 16; kk++) {
            float4 a4 = *reinterpret_cast<const float4*>(&Xs[kk * 64 + tx * 4]);
            float4 b0 = *reinterpret_cast<const float4*>(&Ws[kk * 132 + ty * 8]);
            float4 b1 = *reinterpret_cast<const float4*>(&Ws[kk * 132 + ty * 8 + 4]);
            float av[4] = { a4.x, a4.y, a4.z, a4.w };
            float bv[8] = { b0.x, b0.y, b0.z, b0.w, b1.x, b1.y, b1.z, b1.w };
            #pragma unroll
            for (int i = 0; i < 8; i++)
                #pragma unroll
                for (int j = 0; j < 4; j++)
                    acc[i][j] += bv[i] * av[j];
        }
        __syncthreads();
    }
    float invW = 2.f / (float)(W - 1), invH = 2.f / (float)(H - 1);
    #pragma unroll
    for (int i = 0; i < 8; i++) {
        int oc = oc0 + ty * 8 + i;
        float cx = w[(size_t)oc * Cp2 + C];
        float cy = w[(size_t)oc * Cp2 + C + 1];
        float bb = bias[oc];
        #pragma unroll
        for (int j = 0; j < 4; j++) {
            int p = p0 + tx * 4 + j;
            float xg = -1.f + (float)(p % W) * invW;
            float yg = -1.f + (float)(p / W) * invH;
            o[(size_t)(b * OC + oc) * HW + p] = acc[i][j] + cx * xg + cy * yg + bb;
        }
    }
}

__global__ __launch_bounds__(256) void conv_all_kernel(
    const float* __restrict__ w1, const float* __restrict__ b1,
    const float* __restrict__ w2, const float* __restrict__ b2,
    const float* __restrict__ w3, const float* __restrict__ b3) {
    __shared__ float Xs[16 * 64];
    __shared__ float Ws[16 * 132];
    int id = blockIdx.x, t = threadIdx.x;
    if (id < 512) {
        int b = id >> 7, rem = id & 127;
        conv_body(g_pool0, w1, b1, g_conv0, 256, 256, 64, 64,
                  b, rem & 63, rem >> 6, Xs, Ws, t);
    } else if (id < 768) {
        int v = id - 512;
        int b = v >> 6, rem = v & 63;
        conv_body(g_pool1, w2, b2, g_conv1, 512, 512, 32, 32,
                  b, rem & 15, rem >> 4, Xs, Ws, t);
    } else {
        int v = id - 768;
        int b = v >> 5, rem = v & 31;
        conv_body(g_pool2, w3, b3, g_conv2, 1024, 1024, 16, 16,
                  b, rem & 3, rem >> 2, Xs, Ws, t);
    }
}

// ===================== launch 3: phi (fused resize + out2 + feats) =====================
DI float bilin(const float* __restrict__ sp, int S, int p) {
    int h = p >> 6, ww = p & 63;
    float sc = (float)S / 64.f;
    float fy = ((float)h + 0.5f) * sc - 0.5f; fy = fminf(fmaxf(fy, 0.f), (float)(S - 1));
    float fx = ((float)ww + 0.5f) * sc - 0.5f; fx = fminf(fmaxf(fx, 0.f), (float)(S - 1));
    int y0 = (int)fy, x0 = (int)fx;
    int y1 = min(y0 + 1, S - 1), x1 = min(x0 + 1, S - 1);
    float wy = fy - (float)y0, wx = fx - (float)x0;
    float v00 = sp[y0 * S + x0], v01 = sp[y0 * S + x1];
    float v10 = sp[y1 * S + x0], v11 = sp[y1 * S + x1];
    return (1.f - wy) * ((1.f - wx) * v00 + wx * v01) + wy * ((1.f - wx) * v10 + wx * v11);
}

DI float fetch2(int b, int ch, int p) {
    if (ch < 256)  return g_conv0[(((size_t)(b * 256 + ch)) << 12) + p];
    if (ch < 768)  return bilin(&g_conv1[(size_t)(b * 512 + ch - 256) * 1024], 32, p);
    return bilin(&g_conv2[(size_t)(b * 1024 + ch - 768) * 256], 16, p);
}

__global__ void phi_all_kernel(float* __restrict__ out2) {
    __shared__ float tile[32][33];
    int b = blockIdx.z, ch0 = blockIdx.x * 32, p0 = blockIdx.y * 32;
    int tx = threadIdx.x, ty = threadIdx.y;
    for (int i = ty; i < 32; i += 8) {
        int ch = ch0 + i, p = p0 + tx;
        float v = fetch2(b, ch, p);
        tile[i][tx] = v;
        if (ch < 896)
            out2[(((size_t)(b * 896 + ch)) << 12) + p] = v;
    }
    __syncthreads();
    for (int i = ty; i < 32; i += 8) {
        int p = p0 + i;
        float v = tile[tx][i];
        g_phi[(size_t)(b * 4096 + p) * NCH + ch0 + tx] = __float2bfloat16(v);
        float s = v * v;
        s += __shfl_xor_sync(FULLMASK, s, 16);
        s += __shfl_xor_sync(FULLMASK, s, 8);
        s += __shfl_xor_sync(FULLMASK, s, 4);
        s += __shfl_xor_sync(FULLMASK, s, 2);
        s += __shfl_xor_sync(FULLMASK, s, 1);
        if (tx == 0) atomicAdd(&g_feats[b * 4096 + p], s);
    }
}

// ===================== launch 4: distance GEMM =====================
// CTA 128x128, 256 threads (8 warps 2x4), warp tile 64x32, K-chunk 64,
// 3-stage cp.async, 2 CTAs/SM (smem 110.6KB/CTA, regs <=128)
#define A_STRIDE 144
#define SA_BYTES (128*144)
#define STAGE_BYTES (2*SA_BYTES)          // A + B = 36864
#define NSTAGE 3
#define GEMM_SMEM (NSTAGE*STAGE_BYTES)    // 110592
#define NKCHUNK 28

DI void gemm_load_chunk(uint32_t sbuf, int m0, int n0, int k0, int t) {
    uint32_t sA = sbuf, sB = sbuf + SA_BYTES;
    #pragma unroll
    for (int i = 0; i < 4; i++) {
        int idx = t + i * 256;
        int row = idx >> 3, seg = idx & 7;
        cpasync16(sA + row * A_STRIDE + seg * 16,
                  &g_phi[(size_t)(m0 + row) * NCH + k0 + seg * 8]);
    }
    #pragma unroll
    for (int i = 0; i < 4; i++) {
        int idx = t + i * 256;
        int row = idx >> 3, seg = idx & 7;
        cpasync16(sB + row * A_STRIDE + seg * 16,
                  &g_ct[(size_t)(n0 + row) * NCH + k0 + seg * 8]);
    }
    cp_commit();
}

__global__ __launch_bounds__(256, 2) void gemm_kernel() {
    extern __shared__ __align__(16) char smem[];
    const uint32_t sbase = smem_u32(smem);
    int t = threadIdx.x, lane = t & 31, wid = t >> 5;
    int wm = wid & 1, wn = wid >> 1;     // 2 x 4 warp grid; warp tile 64x32
    int m0 = blockIdx.x * 128, n0 = blockIdx.y * 128;

    float c[4][4][4];
    #pragma unroll
    for (int i = 0; i < 4; i++)
        #pragma unroll
        for (int j = 0; j < 4; j++)
            #pragma unroll
            for (int r = 0; r < 4; r++) c[i][j][r] = 0.f;

    const uint32_t a_row = wm * 64 + (lane & 15);
    const uint32_t a_base = a_row * A_STRIDE + ((lane >> 4) * 16);
    const uint32_t b_row = wn * 32 + ((lane >> 4) * 8) + (lane & 7);
    const uint32_t b_base = b_row * A_STRIDE + (((lane >> 3) & 1) * 16);

    gemm_load_chunk(sbase, m0, n0, 0, t);
    gemm_load_chunk(sbase + STAGE_BYTES, m0, n0, 64, t);

    int stage = 0;
    #pragma unroll 1
    for (int ck = 0; ck < NKCHUNK; ck++) {
        if (ck == NKCHUNK - 1) cp_wait0(); else cp_wait1();
        __syncthreads();
        if (ck + 2 < NKCHUNK) {
            int ls = stage + 2; if (ls >= NSTAGE) ls -= NSTAGE;
            gemm_load_chunk(sbase + ls * STAGE_BYTES, m0, n0, (ck + 2) * 64, t);
        }
        uint32_t sA = sbase + stage * STAGE_BYTES;
        uint32_t sB = sA + SA_BYTES;
        #pragma unroll
        for (int ks = 0; ks < 4; ks++) {
            uint32_t a[4][4];
            #pragma unroll
            for (int mi = 0; mi < 4; mi++)
                ldsm4(a[mi], sA + a_base + mi * (16 * A_STRIDE) + ks * 32);
            uint32_t bfr[2][4];
            #pragma unroll
            for (int np = 0; np < 2; np++)
                ldsm4(bfr[np], sB + b_base + np * (16 * A_STRIDE) + ks * 32);
            #pragma unroll
            for (int mi = 0; mi < 4; mi++)
                #pragma unroll
                for (int np = 0; np < 2; np++) {
                    mma16816(c[mi][np * 2 + 0], a[mi], bfr[np][0], bfr[np][1]);
                    mma16816(c[mi][np * 2 + 1], a[mi], bfr[np][2], bfr[np][3]);
                }
        }
        if (++stage >= NSTAGE) stage = 0;
    }

    #pragma unroll
    for (int mi = 0; mi < 4; mi++) {
        int r0 = m0 + wm * 64 + mi * 16 + (lane >> 2);
        float f0 = g_feats[r0], f1 = g_feats[r0 + 8];
        #pragma unroll
        for (int ni = 0; ni < 4; ni++) {
            int cc = n0 + wn * 32 + ni * 8 + (lane & 3) * 2;
            float ce0 = g_cents[cc], ce1 = g_cents[cc + 1];
            float* dp = &g_dist2[(size_t)r0 * 4096 + cc];
            float2 v0 = { f0 + ce0 - 2.f * c[mi][ni][0], f0 + ce1 - 2.f * c[mi][ni][1] };
            float2 v1 = { f1 + ce0 - 2.f * c[mi][ni][2], f1 + ce1 - 2.f * c[mi][ni][3] };
            *reinterpret_cast<float2*>(dp) = v0;
            *reinterpret_cast<float2*>(dp + (size_t)8 * 4096) = v1;
        }
    }
}

// ===================== launch 5: top-200 per row =====================
__global__ __launch_bounds__(256) void topk_kernel(float* __restrict__ out) {
    __shared__ float keys[4096];
    __shared__ unsigned hist[256];
    __shared__ unsigned scan[256];
    __shared__ unsigned sh_want, sh_prefix;
    __shared__ unsigned cnt_lt;
    __shared__ float sel[256];

    int row = blockIdx.x;
    int t = threadIdx.x;
    int lane = t & 31;
    const float4* src4 = reinterpret_cast<const float4*>(&g_dist2[(size_t)row * 4096]);
    for (int i = t; i < 1024; i += 256) {
        float4 v = src4[i];
        keys[i * 4 + 0] = v.x; keys[i * 4 + 1] = v.y;
        keys[i * 4 + 2] = v.z; keys[i * 4 + 3] = v.w;
    }
    if (t == 0) { sh_want = NNEI; sh_prefix = 0; cnt_lt = 0; }
    __syncthreads();

    for (int pass = 0; pass < 4; pass++) {
        int shift = 24 - pass * 8;
        unsigned pfx = sh_prefix;
        unsigned want = sh_want;
        hist[t] = 0;
        __syncthreads();
        for (int i = t; i < 4096; i += 256) {
            unsigned u = __float_as_uint(keys[i]);
            bool ok = (pass == 0) || ((u >> (shift + 8)) == pfx);
            unsigned d = ok ? ((u >> shift) & 255u) : 0x100u;
            unsigned m = __match_any_sync(FULLMASK, d);
            if (ok && ((m & ((1u << lane) - 1u)) == 0))
                atomicAdd(&hist[d], (unsigned)__popc(m));
        }
        __syncthreads();
        if (t < 32) {
            unsigned vals[8], tot = 0;
            #pragma unroll
            for (int i = 0; i < 8; i++) { vals[i] = hist[t * 8 + i]; tot += vals[i]; }
            unsigned run = tot;
            #pragma unroll
            for (int off = 1; off < 32; off <<= 1) {
                unsigned x = __shfl_up_sync(FULLMASK, run, off);
                if (t >= off) run += x;
            }
            unsigned acc = run - tot;
            #pragma unroll
            for (int i = 0; i < 8; i++) { acc += vals[i]; scan[t * 8 + i] = acc; }
        }
        __syncthreads();
        unsigned below = (t == 0) ? 0u : scan[t - 1];
        if (below < want && want <= scan[t]) {
            sh_want = want - below;
            sh_prefix = (pfx << 8) | (unsigned)t;
        }
        __syncthreads();
    }

    unsigned Tb = sh_prefix;
    float Tf = __uint_as_float(Tb);
    for (int i = t; i < 4096; i += 256) {
        float v = keys[i];
        if (v < Tf) {
            unsigned pos = atomicAdd(&cnt_lt, 1u);
            sel[pos] = v;
        }
    }
    __syncthreads();
    unsigned base = cnt_lt;
    if ((unsigned)t >= base) sel[t] = (t < NNEI) ? Tf : __int_as_float(0x7f800000);
    __syncthreads();

    for (int k = 2; k <= 256; k <<= 1) {
        for (int j = k >> 1; j > 0; j >>= 1) {
            int ixj = t ^ j;
            if (ixj > t) {
                bool up = ((t & k) == 0);
                float a = sel[t], b = sel[ixj];
                if ((a > b) == up) { sel[t] = b; sel[ixj] = a; }
            }
            __syncthreads();
        }
    }

    if (t < NNEI) {
        int b = row >> 12, p = row & 4095;
        out[(((size_t)(b * NNEI + t)) << 12) + p] = sqrtf(sel[t]);
    }
}

// ===================== host launcher =====================
extern "C" void kernel_launch(void* const* d_in, const int* in_sizes, int n_in,
                              void* d_out, int out_size) {
    const float* p0 = (const float*)d_in[0];
    const float* p1 = (const float*)d_in[1];
    const float* p2 = (const float*)d_in[2];
    const float* w1 = (const float*)d_in[5];
    const float* b1 = (const float*)d_in[6];
    const float* w2 = (const float*)d_in[7];
    const float* b2 = (const float*)d_in[8];
    const float* w3 = (const float*)d_in[9];
    const float* b3 = (const float*)d_in[10];
    const float* Cm = (const float*)d_in[11];
    float* score = (float*)d_out;
    float* out2  = score + SCORE_ELEMS;

    static bool attr_set = false;
    if (!attr_set) {
        cudaFuncSetAttribute(gemm_kernel, cudaFuncAttributeMaxDynamicSharedMemorySize, GEMM_SMEM);
        attr_set = true;
    }

    prep_kernel<<<36032, 256>>>(p0, p1, p2, Cm);
    conv_all_kernel<<<896, 256>>>(w1, b1, w2, b2, w3, b3);
    phi_all_kernel<<<dim3(NCH/32, 128, 4), dim3(32, 8)>>>(out2);
    gemm_kernel<<<dim3(M_TOT/128, NCENT/128), 256, GEMM_SMEM>>>();
    topk_kernel<<<M_TOT, 256>>>(score);
}